// round 1
// baseline (speedup 1.0000x reference)
#include <cuda_runtime.h>
#include <math.h>

// Problem constants
#define NB   2
#define LSEQ 1024
#define HH   8
#define DHD  64
#define DDIM 512
#define TCH  128           // chunk length
#define NCH  8             // chunks per sequence (LSEQ/TCH)
#define NHH  16            // NB*HH
#define MROWS (NB*LSEQ)    // 2048
#define SROW 8320          // per-chunk state: 128 feat * 64 val + 128 den

// Device scratch (no cudaMalloc allowed)
__device__ float g_WT[3][DDIM*DDIM];
__device__ float g_Q[MROWS*DDIM];
__device__ float g_K[MROWS*DDIM];
__device__ float g_V[MROWS*DDIM];
__device__ float g_S[NHH*NCH*SROW];

__device__ __forceinline__ float softplus_f(float x) {
    // stable: max(x,0) + log1p(exp(-|x|))
    return fmaxf(x, 0.0f) + log1pf(expf(-fabsf(x)));
}

// ---------------------------------------------------------------------------
// Kernel T: transpose the three 512x512 weights (E,K)->(K,E) so GEMM B-tiles
// are k-major (coalesced global reads, conflict-free smem).
// ---------------------------------------------------------------------------
__global__ void transpose_w_kernel(const float* __restrict__ Wq,
                                   const float* __restrict__ Wk,
                                   const float* __restrict__ Wv) {
    __shared__ float tile[32][33];
    const float* W = (blockIdx.z == 0) ? Wq : (blockIdx.z == 1) ? Wk : Wv;
    float* out = g_WT[blockIdx.z];
    int tx = threadIdx.x, ty = threadIdx.y;
    int bx = blockIdx.x, by = blockIdx.y;
#pragma unroll
    for (int j = ty; j < 32; j += 8)
        tile[j][tx] = W[(by*32 + j)*DDIM + bx*32 + tx];
    __syncthreads();
#pragma unroll
    for (int j = ty; j < 32; j += 8)
        out[(bx*32 + j)*DDIM + by*32 + tx] = tile[tx][j];
}

// ---------------------------------------------------------------------------
// Kernel G: projection GEMM  out[m][e] = sum_k A[m][k] * WT[k][e]
// z = 0: Q = softplus(query@WqT), 1: K = softplus(key@WkT), 2: V = key@WvT
// BM=BN=64, BK=32, 256 threads, 4x4 microtile.
// ---------------------------------------------------------------------------
__global__ __launch_bounds__(256) void proj_gemm_kernel(
        const float* __restrict__ query, const float* __restrict__ key) {
    int which = blockIdx.z;
    const float* __restrict__ A = (which == 0) ? query : key;
    const float* __restrict__ WT = g_WT[which];
    float* __restrict__ out = (which == 0) ? g_Q : (which == 1) ? g_K : g_V;

    __shared__ __align__(16) float sA[32][68]; // [kk][m], padded pitch
    __shared__ __align__(16) float sB[32][64]; // [kk][e]

    int tid = threadIdx.x;
    int am0 = blockIdx.x * 64;
    int bn0 = blockIdx.y * 64;
    int tx = tid & 15, ty = tid >> 4;
    int r0 = ty * 4, c0 = tx * 4;
    float acc[4][4] = {};

    for (int k0 = 0; k0 < DDIM; k0 += 32) {
#pragma unroll
        for (int j = 0; j < 2; j++) {
            int f4 = tid + 256 * j;
            int m  = f4 >> 3;
            int kq = (f4 & 7) << 2;
            float4 v = *(const float4*)&A[(am0 + m) * DDIM + k0 + kq];
            sA[kq + 0][m] = v.x; sA[kq + 1][m] = v.y;
            sA[kq + 2][m] = v.z; sA[kq + 3][m] = v.w;
        }
#pragma unroll
        for (int j = 0; j < 2; j++) {
            int f4 = tid + 256 * j;
            int kk = f4 >> 4;
            int e4 = (f4 & 15) << 2;
            *(float4*)&sB[kk][e4] = *(const float4*)&WT[(k0 + kk) * DDIM + bn0 + e4];
        }
        __syncthreads();
#pragma unroll
        for (int kk = 0; kk < 32; kk++) {
            float4 a = *(const float4*)&sA[kk][r0];
            float4 b = *(const float4*)&sB[kk][c0];
            float av[4] = {a.x, a.y, a.z, a.w};
            float bv[4] = {b.x, b.y, b.z, b.w};
#pragma unroll
            for (int i = 0; i < 4; i++)
#pragma unroll
                for (int jj = 0; jj < 4; jj++)
                    acc[i][jj] = fmaf(av[i], bv[jj], acc[i][jj]);
        }
        __syncthreads();
    }

    bool act = (which < 2);
#pragma unroll
    for (int i = 0; i < 4; i++) {
        float4 v;
        if (act) {
            v.x = softplus_f(acc[i][0]); v.y = softplus_f(acc[i][1]);
            v.z = softplus_f(acc[i][2]); v.w = softplus_f(acc[i][3]);
        } else {
            v.x = acc[i][0]; v.y = acc[i][1]; v.z = acc[i][2]; v.w = acc[i][3];
        }
        *(float4*)&out[(am0 + r0 + i) * DDIM + bn0 + c0] = v;
    }
}

// ---------------------------------------------------------------------------
// Kernel B: per-chunk KV state.  S_c[f][e] = sum_t phik[t][f] * v[t][e],
// plus den column sden_c[f] = sum_t phik[t][f].   block = (nh, c)
// ---------------------------------------------------------------------------
__global__ __launch_bounds__(256) void chunk_state_kernel(const float* __restrict__ pw) {
    extern __shared__ __align__(16) float smB[];
    float* sKf = smB;              // [t][f] 128x128
    float* sV  = smB + 128*128;    // [t][e] 128x64

    int nh = blockIdx.x, c = blockIdx.y;
    int n = nh >> 3, h = nh & 7;
    int tid = threadIdx.x;

    for (int idx = tid; idx < 128*64; idx += 256) {
        int t = idx >> 6, di = idx & 63;
        int tg = c * TCH + t;
        int gbase = ((n << 10) + tg) * DDIM + (h << 6) + di;
        float kv = g_K[gbase];
        float vv = g_V[gbase];
        float w  = pw[(h << 6) + di];
        float s, cs;
        sincosf((float)tg * w, &s, &cs);
        sKf[t*128 + di]      = kv * cs;
        sKf[t*128 + 64 + di] = kv * s;
        sV[idx] = vv;
    }
    __syncthreads();

    int e0 = (tid & 15) << 2;
    int f0 = (tid >> 4) << 3;
    float acc[8][4] = {};
#pragma unroll 4
    for (int t = 0; t < 128; t++) {
        float4 ka = *(const float4*)&sKf[t*128 + f0];
        float4 kb = *(const float4*)&sKf[t*128 + f0 + 4];
        float4 vv = *(const float4*)&sV[t*64 + e0];
        float kf[8] = {ka.x, ka.y, ka.z, ka.w, kb.x, kb.y, kb.z, kb.w};
        float ve[4] = {vv.x, vv.y, vv.z, vv.w};
#pragma unroll
        for (int i = 0; i < 8; i++)
#pragma unroll
            for (int j = 0; j < 4; j++)
                acc[i][j] = fmaf(kf[i], ve[j], acc[i][j]);
    }
    size_t base = (size_t)(nh * NCH + c) * SROW;
#pragma unroll
    for (int i = 0; i < 8; i++) {
        *(float4*)&g_S[base + (size_t)(f0 + i) * 64 + e0] =
            make_float4(acc[i][0], acc[i][1], acc[i][2], acc[i][3]);
    }
    if (tid < 128) {
        float s = 0.0f;
        for (int t = 0; t < 128; t++) s += sKf[t*128 + tid];
        g_S[base + 8192 + tid] = s;
    }
}

// ---------------------------------------------------------------------------
// Kernel D: per-chunk output.
//  A = PhiQ @ PhiK^T (causal-masked within chunk), out = A@V + PhiQ@Prefix,
//  den = rowsum(A) + PhiQ@PrefixDen, write out = num/den (transposed layout).
//  block = (nh, c).  smem: sQT 64K | sKT->sAT 64K | sV 32K | sP 32K | den 1K
// ---------------------------------------------------------------------------
__global__ __launch_bounds__(256, 1) void attn_out_kernel(
        const float* __restrict__ pw, const float* __restrict__ pb,
        const float* __restrict__ coeff, float* __restrict__ out) {
    extern __shared__ __align__(16) float smD[];
    float* sQT   = smD;                  // [f][t] 128x128
    float* sKT   = smD + 16384;          // [f][t], reused as sAT[c][r]
    float* sV    = smD + 32768;          // [t][e] 128x64
    float* sP    = smD + 32768 + 8192;   // [f][e] 128x64, then sPden (contig)
    float* sPden = sP + 8192;            // [128]
    float* sDen  = sPden + 128;          // [128]

    int nh = blockIdx.x, c = blockIdx.y;
    int n = nh >> 3, h = nh & 7;
    int tid = threadIdx.x;

    if (tid < 128) sDen[tid] = 0.0f;

    // Phase 1a: features + V
    for (int idx = tid; idx < 128*64; idx += 256) {
        int t = idx >> 6, di = idx & 63;
        int tg = c * TCH + t;
        int gbase = ((n << 10) + tg) * DDIM + (h << 6) + di;
        float qv = g_Q[gbase], kv = g_K[gbase], vv = g_V[gbase];
        float w  = pw[(h << 6) + di];
        float b  = pb[(h << 6) + di];
        float cf = coeff[(h << 6) + di];
        float sq, cq, sk, ck;
        sincosf((float)tg * w + b, &sq, &cq);
        sincosf((float)tg * w,     &sk, &ck);
        float qc = qv * cf;
        sQT[di*128 + t]        = qc * cq;
        sQT[(64 + di)*128 + t] = qc * sq;
        sKT[di*128 + t]        = kv * ck;
        sKT[(64 + di)*128 + t] = kv * sk;
        sV[idx] = vv;
    }
    // Phase 1b: prefix state = sum of chunk states before c (cp-outer for MLP).
    // sP and sPden are contiguous: treat as one 8320-float region.
    for (int idx = tid; idx < SROW; idx += 256) sP[idx] = 0.0f;
    {
        size_t sb = (size_t)nh * NCH * SROW;
        for (int cp = 0; cp < c; cp++) {
            const float* src = &g_S[sb + (size_t)cp * SROW];
            for (int idx = tid; idx < SROW; idx += 256)
                sP[idx] += src[idx];   // same-thread ownership, no race
        }
    }
    __syncthreads();

    // Phase 2: A = QK^T  (8x8 microtile over 128x128)
    int c0 = (tid & 15) << 3;
    int r0 = (tid >> 4) << 3;
    float acc[8][8] = {};
#pragma unroll 2
    for (int f = 0; f < 128; f++) {
        float4 qa = *(const float4*)&sQT[f*128 + r0];
        float4 qb = *(const float4*)&sQT[f*128 + r0 + 4];
        float4 ka = *(const float4*)&sKT[f*128 + c0];
        float4 kb = *(const float4*)&sKT[f*128 + c0 + 4];
        float qf[8] = {qa.x, qa.y, qa.z, qa.w, qb.x, qb.y, qb.z, qb.w};
        float kf[8] = {ka.x, ka.y, ka.z, ka.w, kb.x, kb.y, kb.z, kb.w};
#pragma unroll
        for (int i = 0; i < 8; i++)
#pragma unroll
            for (int j = 0; j < 8; j++)
                acc[i][j] = fmaf(qf[i], kf[j], acc[i][j]);
    }
    __syncthreads();  // everyone done reading sKT before overwrite

    float* sAT = sKT;  // store masked A transposed: sAT[col][row]
    float rsum[8] = {};
#pragma unroll
    for (int j = 0; j < 8; j++) {
        float col[8];
#pragma unroll
        for (int i = 0; i < 8; i++) {
            float v = ((c0 + j) <= (r0 + i)) ? acc[i][j] : 0.0f;
            col[i] = v; rsum[i] += v;
        }
        *(float4*)&sAT[(c0 + j)*128 + r0]     = make_float4(col[0], col[1], col[2], col[3]);
        *(float4*)&sAT[(c0 + j)*128 + r0 + 4] = make_float4(col[4], col[5], col[6], col[7]);
    }
#pragma unroll
    for (int i = 0; i < 8; i++) atomicAdd(&sDen[r0 + i], rsum[i]);
    __syncthreads();

    // Phase 3: out = Amask@V + QT^T@P  (8x4 microtile over 128x64)
    int e0 = (tid & 15) << 2;
    float o[8][4] = {};
#pragma unroll 2
    for (int tp = 0; tp < 128; tp++) {
        float4 a0 = *(const float4*)&sAT[tp*128 + r0];
        float4 a1 = *(const float4*)&sAT[tp*128 + r0 + 4];
        float4 vv = *(const float4*)&sV[tp*64 + e0];
        float af[8] = {a0.x, a0.y, a0.z, a0.w, a1.x, a1.y, a1.z, a1.w};
        float ve[4] = {vv.x, vv.y, vv.z, vv.w};
#pragma unroll
        for (int i = 0; i < 8; i++)
#pragma unroll
            for (int j = 0; j < 4; j++)
                o[i][j] = fmaf(af[i], ve[j], o[i][j]);
    }
#pragma unroll 2
    for (int f = 0; f < 128; f++) {
        float4 q0 = *(const float4*)&sQT[f*128 + r0];
        float4 q1 = *(const float4*)&sQT[f*128 + r0 + 4];
        float4 pp = *(const float4*)&sP[f*64 + e0];
        float qf[8] = {q0.x, q0.y, q0.z, q0.w, q1.x, q1.y, q1.z, q1.w};
        float pe[4] = {pp.x, pp.y, pp.z, pp.w};
#pragma unroll
        for (int i = 0; i < 8; i++)
#pragma unroll
            for (int j = 0; j < 4; j++)
                o[i][j] = fmaf(qf[i], pe[j], o[i][j]);
    }
    // den inter-chunk: den[t] += sum_f QT[f][t] * Pden[f]
    if (tid < 128) {
        float s = 0.0f;
        for (int f = 0; f < 128; f++) s += sQT[f*128 + tid] * sPden[f];
        sDen[tid] += s;
    }
    __syncthreads();

    // Phase 4: normalize + write (N, Lq, H*dh) layout
#pragma unroll
    for (int i = 0; i < 8; i++) {
        int t = r0 + i;
        float inv = 1.0f / sDen[t];
        int tg = c * TCH + t;
        float4 v = make_float4(o[i][0]*inv, o[i][1]*inv, o[i][2]*inv, o[i][3]*inv);
        *(float4*)&out[((n << 10) + tg) * DDIM + (h << 6) + e0] = v;
    }
}

// ---------------------------------------------------------------------------
extern "C" void kernel_launch(void* const* d_in, const int* in_sizes, int n_in,
                              void* d_out, int out_size) {
    const float* query = (const float*)d_in[0];
    const float* key   = (const float*)d_in[1];
    const float* Wq    = (const float*)d_in[2];
    const float* Wk    = (const float*)d_in[3];
    const float* Wv    = (const float*)d_in[4];
    const float* coeff = (const float*)d_in[5];
    const float* pw    = (const float*)d_in[6];
    const float* pb    = (const float*)d_in[7];
    float* out = (float*)d_out;

    cudaFuncSetAttribute(chunk_state_kernel,
                         cudaFuncAttributeMaxDynamicSharedMemorySize, 98304);
    cudaFuncSetAttribute(attn_out_kernel,
                         cudaFuncAttributeMaxDynamicSharedMemorySize, 197632);

    transpose_w_kernel<<<dim3(16, 16, 3), dim3(32, 8)>>>(Wq, Wk, Wv);
    proj_gemm_kernel<<<dim3(MROWS/64, DDIM/64, 3), 256>>>(query, key);
    chunk_state_kernel<<<dim3(NHH, NCH), 256, 98304>>>(pw);
    attn_out_kernel<<<dim3(NHH, NCH), 256, 197632>>>(pw, pb, coeff, out);
}

// round 3
// speedup vs baseline: 1.4789x; 1.4789x over previous
#include <cuda_runtime.h>
#include <math.h>
#include <stdint.h>

// Problem constants
#define NB   2
#define LSEQ 1024
#define HH   8
#define DHD  64
#define DDIM 512
#define TCH  128
#define NCH  8
#define NHH  16
#define MROWS (NB*LSEQ)    // 2048
#define SROW 8320          // per-chunk state: 128 feat * 64 val + 128 den

// Device scratch (no cudaMalloc allowed)
__device__ float g_Q[MROWS*DDIM];
__device__ float g_K[MROWS*DDIM];
__device__ float g_V[MROWS*DDIM];
__device__ float g_S[NHH*NCH*SROW];

__device__ __forceinline__ float softplus_f(float x) {
    return fmaxf(x, 0.0f) + log1pf(expf(-fabsf(x)));
}

// ---------------------------------------------------------------------------
// sm_80-era primitives (compile clean for compute_103 baseline target)
// ---------------------------------------------------------------------------
__device__ __forceinline__ uint32_t smem_u32(const void* p) {
    uint32_t a;
    asm("{ .reg .u64 t; cvta.to.shared.u64 t, %1; cvt.u32.u64 %0, t; }"
        : "=r"(a) : "l"(p));
    return a;
}
#define CP_ASYNC16(dst, src) \
    asm volatile("cp.async.cg.shared.global [%0], [%1], 16;" :: "r"(dst), "l"(src))
#define CP_COMMIT()  asm volatile("cp.async.commit_group;" ::: "memory")
#define CP_WAIT(n)   asm volatile("cp.async.wait_group %0;" :: "n"(n) : "memory")

__device__ __forceinline__ void mma_tf32(float* d, const uint32_t* a, const uint32_t* b) {
    asm volatile(
        "mma.sync.aligned.m16n8k8.row.col.f32.tf32.tf32.f32 "
        "{%0,%1,%2,%3}, {%4,%5,%6,%7}, {%8,%9}, {%0,%1,%2,%3};"
        : "+f"(d[0]), "+f"(d[1]), "+f"(d[2]), "+f"(d[3])
        : "r"(a[0]), "r"(a[1]), "r"(a[2]), "r"(a[3]), "r"(b[0]), "r"(b[1]));
}

// swizzle: k column xor'd by row&7 (units of 4 floats) -> conflict-free frags
__device__ __forceinline__ int swz(int row, int k) { return k ^ ((row & 7) << 2); }

// ---------------------------------------------------------------------------
// Kernel G: projection GEMM via warp-level tf32 mma.
// out[m][e] = sum_k A[m][k] * W[e][k]; A row-major (m,k), W row-major (e,k)
// = mma row.col with B^T = W. Block 128x128, 4 warps (64x64 each), BK=32,
// 2-stage cp.async pipeline. z=0: Q=softplus(q@Wq^T), 1: K=sp(key@Wk^T), 2: V.
// ---------------------------------------------------------------------------
__global__ __launch_bounds__(128) void proj_mma_kernel(
        const float* __restrict__ query, const float* __restrict__ key,
        const float* __restrict__ Wq, const float* __restrict__ Wk,
        const float* __restrict__ Wv) {
    extern __shared__ __align__(16) float sm[];
    // layout: sA[2][128*32] | sB[2][128*32]
    float* sAbuf[2] = { sm, sm + 4096 };
    float* sBbuf[2] = { sm + 8192, sm + 12288 };

    const int which = blockIdx.z;
    const float* __restrict__ A = (which == 0) ? query : key;
    const float* __restrict__ B = (which == 0) ? Wq : (which == 1) ? Wk : Wv;
    float* __restrict__ out = (which == 0) ? g_Q : (which == 1) ? g_K : g_V;
    const int am0 = blockIdx.x * 128;
    const int bn0 = blockIdx.y * 128;

    const int tid = threadIdx.x;
    const int wid = tid >> 5, lane = tid & 31;
    const int gid = lane >> 2, tid4 = lane & 3;
    const int m0 = (wid & 1) * 64;   // warp m offset in tile
    const int n0 = (wid >> 1) * 64;  // warp n offset in tile

    // cp.async issue helper indices (8 float4 per operand per thread per stage)
    const int lrow = tid >> 0;  // dummy to keep compiler happy

    float acc[4][8][4];
#pragma unroll
    for (int i = 0; i < 4; i++)
#pragma unroll
        for (int j = 0; j < 8; j++)
#pragma unroll
            for (int q = 0; q < 4; q++) acc[i][j][q] = 0.0f;

    auto issue_stage = [&](int kt, int buf) {
        const int k0 = kt * 32;
        uint32_t sa = smem_u32(sAbuf[buf]);
        uint32_t sb = smem_u32(sBbuf[buf]);
#pragma unroll
        for (int i = 0; i < 8; i++) {
            int f4 = tid + 128 * i;
            int row = f4 >> 3;         // 0..127
            int k4  = (f4 & 7) << 2;   // 0,4,...,28
            int soff = (row * 32 + swz(row, k4)) * 4;
            CP_ASYNC16(sa + soff, &A[(size_t)(am0 + row) * DDIM + k0 + k4]);
            CP_ASYNC16(sb + soff, &B[(size_t)(bn0 + row) * DDIM + k0 + k4]);
        }
        CP_COMMIT();
    };

    issue_stage(0, 0);

    for (int kt = 0; kt < 16; kt++) {
        const int buf = kt & 1;
        if (kt < 15) issue_stage(kt + 1, buf ^ 1);
        if (kt < 15) CP_WAIT(1); else CP_WAIT(0);
        __syncthreads();

        const uint32_t* sA32 = (const uint32_t*)sAbuf[buf];
        const uint32_t* sB32 = (const uint32_t*)sBbuf[buf];
#pragma unroll
        for (int k8 = 0; k8 < 4; k8++) {
            const int kk = k8 * 8 + tid4;
            uint32_t af[4][4];
#pragma unroll
            for (int mt = 0; mt < 4; mt++) {
                int r = m0 + mt * 16 + gid;
                af[mt][0] = sA32[r * 32 + swz(r, kk)];
                af[mt][1] = sA32[(r + 8) * 32 + swz(r + 8, kk)];
                af[mt][2] = sA32[r * 32 + swz(r, kk + 4)];
                af[mt][3] = sA32[(r + 8) * 32 + swz(r + 8, kk + 4)];
            }
            uint32_t bf[8][2];
#pragma unroll
            for (int nt = 0; nt < 8; nt++) {
                int nn = n0 + nt * 8 + gid;
                bf[nt][0] = sB32[nn * 32 + swz(nn, kk)];
                bf[nt][1] = sB32[nn * 32 + swz(nn, kk + 4)];
            }
#pragma unroll
            for (int mt = 0; mt < 4; mt++)
#pragma unroll
                for (int nt = 0; nt < 8; nt++)
                    mma_tf32(acc[mt][nt], af[mt], bf[nt]);
        }
        __syncthreads();
    }

    // Epilogue: write 64x64 per warp; c0/c1 at (row, col..col+1), c2/c3 at row+8
    const bool act = (which < 2);
#pragma unroll
    for (int mt = 0; mt < 4; mt++) {
#pragma unroll
        for (int nt = 0; nt < 8; nt++) {
            int row = am0 + m0 + mt * 16 + gid;
            int col = bn0 + n0 + nt * 8 + tid4 * 2;
            float v0 = acc[mt][nt][0], v1 = acc[mt][nt][1];
            float v2 = acc[mt][nt][2], v3 = acc[mt][nt][3];
            if (act) {
                v0 = softplus_f(v0); v1 = softplus_f(v1);
                v2 = softplus_f(v2); v3 = softplus_f(v3);
            }
            *(float2*)&out[(size_t)row * DDIM + col] = make_float2(v0, v1);
            *(float2*)&out[(size_t)(row + 8) * DDIM + col] = make_float2(v2, v3);
        }
    }
    (void)lrow;
}

// ---------------------------------------------------------------------------
// Kernel B: per-chunk KV state. S_c[f][e] = sum_t phik[t][f] * v[t][e]
// plus den column. 512 threads, 4x4 microtile.
// ---------------------------------------------------------------------------
__global__ __launch_bounds__(512) void chunk_state_kernel(const float* __restrict__ pw) {
    extern __shared__ __align__(16) float smB[];
    float* sKf = smB;              // [t][f] 128x128
    float* sV  = smB + 128*128;    // [t][e] 128x64

    const int nh = blockIdx.x, c = blockIdx.y;
    const int n = nh >> 3, h = nh & 7;
    const int tid = threadIdx.x;

    for (int idx = tid; idx < 128*64; idx += 512) {
        int t = idx >> 6, di = idx & 63;
        int tg = c * TCH + t;
        int gbase = ((n << 10) + tg) * DDIM + (h << 6) + di;
        float kv = g_K[gbase];
        float vv = g_V[gbase];
        float w  = pw[(h << 6) + di];
        float s, cs;
        sincosf((float)tg * w, &s, &cs);
        sKf[t*128 + di]      = kv * cs;
        sKf[t*128 + 64 + di] = kv * s;
        sV[idx] = vv;
    }
    __syncthreads();

    const int f0 = (tid >> 4) << 2;   // 32 groups of 4 -> 128
    const int e0 = (tid & 15) << 2;   // 16 groups of 4 -> 64
    float acc[4][4] = {};
#pragma unroll 4
    for (int t = 0; t < 128; t++) {
        float4 ka = *(const float4*)&sKf[t*128 + f0];
        float4 vv = *(const float4*)&sV[t*64 + e0];
        float kf[4] = {ka.x, ka.y, ka.z, ka.w};
        float ve[4] = {vv.x, vv.y, vv.z, vv.w};
#pragma unroll
        for (int i = 0; i < 4; i++)
#pragma unroll
            for (int j = 0; j < 4; j++)
                acc[i][j] = fmaf(kf[i], ve[j], acc[i][j]);
    }
    size_t base = (size_t)(nh * NCH + c) * SROW;
#pragma unroll
    for (int i = 0; i < 4; i++)
        *(float4*)&g_S[base + (size_t)(f0 + i) * 64 + e0] =
            make_float4(acc[i][0], acc[i][1], acc[i][2], acc[i][3]);
    if (tid < 128) {
        float s = 0.0f;
        for (int t = 0; t < 128; t++) s += sKf[t*128 + tid];
        g_S[base + 8192 + tid] = s;
    }
}

// ---------------------------------------------------------------------------
// Kernel D: per-chunk output. 512 threads.
// ---------------------------------------------------------------------------
__global__ __launch_bounds__(512, 1) void attn_out_kernel(
        const float* __restrict__ pw, const float* __restrict__ pb,
        const float* __restrict__ coeff, float* __restrict__ out) {
    extern __shared__ __align__(16) float smD[];
    float* sQT   = smD;                  // [f][t] 128x128
    float* sKT   = smD + 16384;          // [f][t], reused as sA[row][col]
    float* sV    = smD + 32768;          // [t][e] 128x64
    float* sP    = smD + 32768 + 8192;   // [f][e] 128x64, contiguous with sPden
    float* sPden = sP + 8192;            // [128]
    float* sDen  = sPden + 128;          // [128]

    const int nh = blockIdx.x, c = blockIdx.y;
    const int n = nh >> 3, h = nh & 7;
    const int tid = threadIdx.x;

    if (tid < 128) sDen[tid] = 0.0f;

    // Phase 1a: features + V
    for (int idx = tid; idx < 128*64; idx += 512) {
        int t = idx >> 6, di = idx & 63;
        int tg = c * TCH + t;
        int gbase = ((n << 10) + tg) * DDIM + (h << 6) + di;
        float qv = g_Q[gbase], kv = g_K[gbase], vv = g_V[gbase];
        float w  = pw[(h << 6) + di];
        float b  = pb[(h << 6) + di];
        float cf = coeff[(h << 6) + di];
        float sq, cq, sk, ck;
        sincosf((float)tg * w + b, &sq, &cq);
        sincosf((float)tg * w,     &sk, &ck);
        float qc = qv * cf;
        sQT[di*128 + t]        = qc * cq;
        sQT[(64 + di)*128 + t] = qc * sq;
        sKT[di*128 + t]        = kv * ck;
        sKT[(64 + di)*128 + t] = kv * sk;
        sV[idx] = vv;
    }
    // Phase 1b: prefix state (register-accumulated)
    {
        size_t sb = (size_t)nh * NCH * SROW;
        for (int idx = tid; idx < SROW; idx += 512) {
            float acc = 0.0f;
            for (int cp = 0; cp < c; cp++)
                acc += g_S[sb + (size_t)cp * SROW + idx];
            sP[idx] = acc;
        }
    }
    __syncthreads();

    // Phase 2: A = QK^T  (8x4 microtile over 128x128, 512 threads)
    const int r0 = (tid >> 5) << 3;
    const int c0 = (tid & 31) << 2;
    float acc[8][4] = {};
#pragma unroll 2
    for (int f = 0; f < 128; f++) {
        float4 qa = *(const float4*)&sQT[f*128 + r0];
        float4 qb = *(const float4*)&sQT[f*128 + r0 + 4];
        float4 ka = *(const float4*)&sKT[f*128 + c0];
        float qf[8] = {qa.x, qa.y, qa.z, qa.w, qb.x, qb.y, qb.z, qb.w};
        float kf[4] = {ka.x, ka.y, ka.z, ka.w};
#pragma unroll
        for (int i = 0; i < 8; i++)
#pragma unroll
            for (int j = 0; j < 4; j++)
                acc[i][j] = fmaf(qf[i], kf[j], acc[i][j]);
    }
    __syncthreads();  // done reading sKT

    float* sA = sKT;  // masked A, row-major [row][col]
#pragma unroll
    for (int i = 0; i < 8; i++) {
        float4 v;
        v.x = (c0 + 0 <= r0 + i) ? acc[i][0] : 0.0f;
        v.y = (c0 + 1 <= r0 + i) ? acc[i][1] : 0.0f;
        v.z = (c0 + 2 <= r0 + i) ? acc[i][2] : 0.0f;
        v.w = (c0 + 3 <= r0 + i) ? acc[i][3] : 0.0f;
        *(float4*)&sA[(r0 + i) * 128 + c0] = v;
        float rs = v.x + v.y + v.z + v.w;
        if (rs != 0.0f) atomicAdd(&sDen[r0 + i], rs);
    }
    __syncthreads();

    // Phase 3: out = A@V + QT^T@P  (4x4 microtile over 128x64)
    const int r3 = (tid >> 4) << 2;
    const int e0 = (tid & 15) << 2;
    float o[4][4] = {};
#pragma unroll 2
    for (int tp = 0; tp < 128; tp++) {
        float a0 = sA[(r3 + 0)*128 + tp];
        float a1 = sA[(r3 + 1)*128 + tp];
        float a2 = sA[(r3 + 2)*128 + tp];
        float a3 = sA[(r3 + 3)*128 + tp];
        float4 vv = *(const float4*)&sV[tp*64 + e0];
        float af[4] = {a0, a1, a2, a3};
        float ve[4] = {vv.x, vv.y, vv.z, vv.w};
#pragma unroll
        for (int i = 0; i < 4; i++)
#pragma unroll
            for (int j = 0; j < 4; j++)
                o[i][j] = fmaf(af[i], ve[j], o[i][j]);
    }
#pragma unroll 2
    for (int f = 0; f < 128; f++) {
        float q0 = sQT[f*128 + r3 + 0];
        float q1 = sQT[f*128 + r3 + 1];
        float q2 = sQT[f*128 + r3 + 2];
        float q3 = sQT[f*128 + r3 + 3];
        float4 pp = *(const float4*)&sP[f*64 + e0];
        float qf[4] = {q0, q1, q2, q3};
        float pe[4] = {pp.x, pp.y, pp.z, pp.w};
#pragma unroll
        for (int i = 0; i < 4; i++)
#pragma unroll
            for (int j = 0; j < 4; j++)
                o[i][j] = fmaf(qf[i], pe[j], o[i][j]);
    }
    // den inter-chunk: den[t] += sum_f QT[f][t] * Pden[f]  (4-way split)
    {
        int t = tid & 127, part = tid >> 7;
        float s = 0.0f;
        for (int f = part * 32; f < part * 32 + 32; f++)
            s += sQT[f*128 + t] * sPden[f];
        atomicAdd(&sDen[t], s);
    }
    __syncthreads();

    // Phase 4: normalize + write (N, Lq, H*dh)
#pragma unroll
    for (int i = 0; i < 4; i++) {
        int t = r3 + i;
        float inv = 1.0f / sDen[t];
        int tg = c * TCH + t;
        float4 v = make_float4(o[i][0]*inv, o[i][1]*inv, o[i][2]*inv, o[i][3]*inv);
        *(float4*)&out[((n << 10) + tg) * DDIM + (h << 6) + e0] = v;
    }
}

// ---------------------------------------------------------------------------
extern "C" void kernel_launch(void* const* d_in, const int* in_sizes, int n_in,
                              void* d_out, int out_size) {
    const float* query = (const float*)d_in[0];
    const float* key   = (const float*)d_in[1];
    const float* Wq    = (const float*)d_in[2];
    const float* Wk    = (const float*)d_in[3];
    const float* Wv    = (const float*)d_in[4];
    const float* coeff = (const float*)d_in[5];
    const float* pw    = (const float*)d_in[6];
    const float* pb    = (const float*)d_in[7];
    float* out = (float*)d_out;

    cudaFuncSetAttribute(proj_mma_kernel,
                         cudaFuncAttributeMaxDynamicSharedMemorySize, 65536);
    cudaFuncSetAttribute(chunk_state_kernel,
                         cudaFuncAttributeMaxDynamicSharedMemorySize, 98304);
    cudaFuncSetAttribute(attn_out_kernel,
                         cudaFuncAttributeMaxDynamicSharedMemorySize, 197632);

    proj_mma_kernel<<<dim3(MROWS/128, DDIM/128, 3), 128, 65536>>>(query, key, Wq, Wk, Wv);
    chunk_state_kernel<<<dim3(NHH, NCH), 512, 98304>>>(pw);
    attn_out_kernel<<<dim3(NHH, NCH), 512, 197632>>>(pw, pb, coeff, out);
}

// round 4
// speedup vs baseline: 1.9339x; 1.3077x over previous
#include <cuda_runtime.h>
#include <math.h>
#include <stdint.h>

// Problem constants
#define NB   2
#define LSEQ 1024
#define HH   8
#define DHD  64
#define DDIM 512
#define TCH  128
#define NCH  8
#define NHH  16
#define MROWS (NB*LSEQ)    // 2048
#define SROW 8320          // per-chunk state: 128x64 S + 128 den

__device__ float g_Q[MROWS*DDIM];
__device__ float g_K[MROWS*DDIM];
__device__ float g_V[MROWS*DDIM];
__device__ float g_S[NHH*NCH*SROW];

__device__ __forceinline__ float softplus_f(float x) {
    return fmaxf(x, 0.0f) + log1pf(expf(-fabsf(x)));
}

// ---------------------------------------------------------------------------
// sm_80-era primitives (compile clean for compute_103 baseline target)
// ---------------------------------------------------------------------------
__device__ __forceinline__ uint32_t smem_u32(const void* p) {
    uint32_t a;
    asm("{ .reg .u64 t; cvta.to.shared.u64 t, %1; cvt.u32.u64 %0, t; }"
        : "=r"(a) : "l"(p));
    return a;
}
#define CP_ASYNC16(dst, src) \
    asm volatile("cp.async.cg.shared.global [%0], [%1], 16;" :: "r"(dst), "l"(src))
#define CP_COMMIT()  asm volatile("cp.async.commit_group;" ::: "memory")
#define CP_WAIT(n)   asm volatile("cp.async.wait_group %0;" :: "n"(n) : "memory")

__device__ __forceinline__ void mma_tf32(float* d, const uint32_t* a, const uint32_t* b) {
    asm volatile(
        "mma.sync.aligned.m16n8k8.row.col.f32.tf32.tf32.f32 "
        "{%0,%1,%2,%3}, {%4,%5,%6,%7}, {%8,%9}, {%0,%1,%2,%3};"
        : "+f"(d[0]), "+f"(d[1]), "+f"(d[2]), "+f"(d[3])
        : "r"(a[0]), "r"(a[1]), "r"(a[2]), "r"(a[3]), "r"(b[0]), "r"(b[1]));
}
// round-to-nearest fp32 -> tf32 (unbiased; critical for accuracy)
__device__ __forceinline__ uint32_t f2tf(float x) {
    uint32_t r;
    asm("cvt.rna.tf32.f32 %0, %1;" : "=r"(r) : "f"(x));
    return r;
}
// swizzle for proj smem: k column xor'd by row&7 (units of 4 floats)
__device__ __forceinline__ int swz(int row, int k) { return k ^ ((row & 7) << 2); }

// Padded strides for attention smem (conflict-free mma fragment LDS)
#define SFT 132   // feature-major stride (128 + 4)
#define SVE 68    // value stride (64 + 4)

// ---------------------------------------------------------------------------
// Kernel G: projection GEMM via warp tf32 mma, 256 threads, 8 warps 64x32.
// out[m][e] = sum_k A[m][k]*W[e][k]. z=0:Q=sp, 1:K=sp, 2:V.
// ---------------------------------------------------------------------------
__global__ __launch_bounds__(256) void proj_mma_kernel(
        const float* __restrict__ query, const float* __restrict__ key,
        const float* __restrict__ Wq, const float* __restrict__ Wk,
        const float* __restrict__ Wv) {
    extern __shared__ __align__(16) float sm[];
    float* sAbuf[2] = { sm, sm + 4096 };
    float* sBbuf[2] = { sm + 8192, sm + 12288 };

    const int which = blockIdx.z;
    const float* __restrict__ A = (which == 0) ? query : key;
    const float* __restrict__ B = (which == 0) ? Wq : (which == 1) ? Wk : Wv;
    float* __restrict__ out = (which == 0) ? g_Q : (which == 1) ? g_K : g_V;
    const int am0 = blockIdx.x * 128;
    const int bn0 = blockIdx.y * 128;

    const int tid = threadIdx.x;
    const int wid = tid >> 5, lane = tid & 31;
    const int gid = lane >> 2, tid4 = lane & 3;
    const int m0 = (wid & 1) * 64;
    const int n0 = (wid >> 1) * 32;

    float acc[4][4][4];
#pragma unroll
    for (int i = 0; i < 4; i++)
#pragma unroll
        for (int j = 0; j < 4; j++)
#pragma unroll
            for (int q = 0; q < 4; q++) acc[i][j][q] = 0.0f;

    auto issue_stage = [&](int kt, int buf) {
        const int k0 = kt * 32;
        uint32_t sa = smem_u32(sAbuf[buf]);
        uint32_t sb = smem_u32(sBbuf[buf]);
#pragma unroll
        for (int i = 0; i < 4; i++) {
            int f4 = tid + 256 * i;
            int row = f4 >> 3;
            int k4  = (f4 & 7) << 2;
            int soff = (row * 32 + swz(row, k4)) * 4;
            CP_ASYNC16(sa + soff, &A[(size_t)(am0 + row) * DDIM + k0 + k4]);
            CP_ASYNC16(sb + soff, &B[(size_t)(bn0 + row) * DDIM + k0 + k4]);
        }
        CP_COMMIT();
    };

    issue_stage(0, 0);

    for (int kt = 0; kt < 16; kt++) {
        const int buf = kt & 1;
        if (kt < 15) issue_stage(kt + 1, buf ^ 1);
        if (kt < 15) CP_WAIT(1); else CP_WAIT(0);
        __syncthreads();

        const float* sA = sAbuf[buf];
        const float* sB = sBbuf[buf];
#pragma unroll
        for (int k8 = 0; k8 < 4; k8++) {
            const int kk = k8 * 8 + tid4;
            uint32_t af[4][4];
#pragma unroll
            for (int mt = 0; mt < 4; mt++) {
                int r = m0 + mt * 16 + gid;
                af[mt][0] = f2tf(sA[r * 32 + swz(r, kk)]);
                af[mt][1] = f2tf(sA[(r + 8) * 32 + swz(r + 8, kk)]);
                af[mt][2] = f2tf(sA[r * 32 + swz(r, kk + 4)]);
                af[mt][3] = f2tf(sA[(r + 8) * 32 + swz(r + 8, kk + 4)]);
            }
            uint32_t bf[4][2];
#pragma unroll
            for (int nt = 0; nt < 4; nt++) {
                int nn = n0 + nt * 8 + gid;
                bf[nt][0] = f2tf(sB[nn * 32 + swz(nn, kk)]);
                bf[nt][1] = f2tf(sB[nn * 32 + swz(nn, kk + 4)]);
            }
#pragma unroll
            for (int mt = 0; mt < 4; mt++)
#pragma unroll
                for (int nt = 0; nt < 4; nt++)
                    mma_tf32(acc[mt][nt], af[mt], bf[nt]);
        }
        __syncthreads();
    }

    const bool act = (which < 2);
#pragma unroll
    for (int mt = 0; mt < 4; mt++) {
#pragma unroll
        for (int nt = 0; nt < 4; nt++) {
            int row = am0 + m0 + mt * 16 + gid;
            int col = bn0 + n0 + nt * 8 + tid4 * 2;
            float v0 = acc[mt][nt][0], v1 = acc[mt][nt][1];
            float v2 = acc[mt][nt][2], v3 = acc[mt][nt][3];
            if (act) {
                v0 = softplus_f(v0); v1 = softplus_f(v1);
                v2 = softplus_f(v2); v3 = softplus_f(v3);
            }
            *(float2*)&out[(size_t)row * DDIM + col] = make_float2(v0, v1);
            *(float2*)&out[(size_t)(row + 8) * DDIM + col] = make_float2(v2, v3);
        }
    }
}

// ---------------------------------------------------------------------------
// Kernel B: per-chunk KV state via warp mma. S[f][e] = sum_t Kf[t][f]*V[t][e]
// 512 threads, 16 warps, warp tile 32x16.
// ---------------------------------------------------------------------------
__global__ __launch_bounds__(512) void chunk_state_kernel(const float* __restrict__ pw) {
    extern __shared__ __align__(16) float smB[];
    float* sKf = smB;                // [t][f] stride SFT
    float* sV  = smB + 128*SFT;      // [t][e] stride SVE

    const int nh = blockIdx.x, c = blockIdx.y;
    const int n = nh >> 3, h = nh & 7;
    const int tid = threadIdx.x;
    const int wid = tid >> 5, lane = tid & 31;
    const int gid = lane >> 2, tid4 = lane & 3;

    for (int idx = tid; idx < 128*64; idx += 512) {
        int t = idx >> 6, di = idx & 63;
        int tg = c * TCH + t;
        int gbase = ((n << 10) + tg) * DDIM + (h << 6) + di;
        float kv = g_K[gbase];
        float vv = g_V[gbase];
        float w  = pw[(h << 6) + di];
        float s, cs;
        sincosf((float)tg * w, &s, &cs);
        sKf[t*SFT + di]      = kv * cs;
        sKf[t*SFT + 64 + di] = kv * s;
        sV[t*SVE + di] = vv;
    }
    __syncthreads();

    // A[f][t] = sKf[t][f] (k-major in smem), B[e][t] = sV[t][e]
    const int m0 = (wid & 3) * 32;
    const int n0 = (wid >> 2) * 16;
    float acc[2][2][4] = {};
#pragma unroll
    for (int k8 = 0; k8 < 16; k8++) {
        const int kk = k8 * 8 + tid4;
        uint32_t af[2][4];
#pragma unroll
        for (int mt = 0; mt < 2; mt++) {
            int r = m0 + mt * 16 + gid;
            af[mt][0] = f2tf(sKf[kk*SFT + r]);
            af[mt][1] = f2tf(sKf[kk*SFT + r + 8]);
            af[mt][2] = f2tf(sKf[(kk+4)*SFT + r]);
            af[mt][3] = f2tf(sKf[(kk+4)*SFT + r + 8]);
        }
        uint32_t bf[2][2];
#pragma unroll
        for (int nt = 0; nt < 2; nt++) {
            int nn = n0 + nt * 8 + gid;
            bf[nt][0] = f2tf(sV[kk*SVE + nn]);
            bf[nt][1] = f2tf(sV[(kk+4)*SVE + nn]);
        }
#pragma unroll
        for (int mt = 0; mt < 2; mt++)
#pragma unroll
            for (int nt = 0; nt < 2; nt++)
                mma_tf32(acc[mt][nt], af[mt], bf[nt]);
    }
    size_t base = (size_t)(nh * NCH + c) * SROW;
#pragma unroll
    for (int mt = 0; mt < 2; mt++) {
#pragma unroll
        for (int nt = 0; nt < 2; nt++) {
            int f = m0 + mt * 16 + gid;
            int e = n0 + nt * 8 + tid4 * 2;
            *(float2*)&g_S[base + (size_t)f * 64 + e] =
                make_float2(acc[mt][nt][0], acc[mt][nt][1]);
            *(float2*)&g_S[base + (size_t)(f + 8) * 64 + e] =
                make_float2(acc[mt][nt][2], acc[mt][nt][3]);
        }
    }
    if (tid < 128) {
        float s = 0.0f;
        for (int t = 0; t < 128; t++) s += sKf[t*SFT + tid];
        g_S[base + 8192 + tid] = s;
    }
}

// ---------------------------------------------------------------------------
// Kernel D: per-chunk output, all GEMMs via warp mma. 512 threads, 16 warps.
// ---------------------------------------------------------------------------
__global__ __launch_bounds__(512, 1) void attn_out_kernel(
        const float* __restrict__ pw, const float* __restrict__ pb,
        const float* __restrict__ coeff, float* __restrict__ out) {
    extern __shared__ __align__(16) float smD[];
    float* sQT   = smD;                   // [f][t] stride SFT (16896)
    float* sKT   = smD + 16896;           // [f][t] stride SFT, reused as sA[t][t'] stride SFT
    float* sV    = smD + 33792;           // [t][e] stride SVE (8704)
    float* sP    = smD + 42496;           // [f][e] stride SVE (8704)
    float* sPden = smD + 51200;           // [128]
    float* sDen  = smD + 51328;           // [128]

    const int nh = blockIdx.x, c = blockIdx.y;
    const int n = nh >> 3, h = nh & 7;
    const int tid = threadIdx.x;
    const int wid = tid >> 5, lane = tid & 31;
    const int gid = lane >> 2, tid4 = lane & 3;

    if (tid < 128) sDen[tid] = 0.0f;

    // Phase 1a: features + V
    for (int idx = tid; idx < 128*64; idx += 512) {
        int t = idx >> 6, di = idx & 63;
        int tg = c * TCH + t;
        int gbase = ((n << 10) + tg) * DDIM + (h << 6) + di;
        float qv = g_Q[gbase], kv = g_K[gbase], vv = g_V[gbase];
        float w  = pw[(h << 6) + di];
        float b  = pb[(h << 6) + di];
        float cf = coeff[(h << 6) + di];
        float sq, cq, sk, ck;
        sincosf((float)tg * w + b, &sq, &cq);
        sincosf((float)tg * w,     &sk, &ck);
        float qc = qv * cf;
        sQT[di*SFT + t]        = qc * cq;
        sQT[(64 + di)*SFT + t] = qc * sq;
        sKT[di*SFT + t]        = kv * ck;
        sKT[(64 + di)*SFT + t] = kv * sk;
        sV[t*SVE + di] = vv;
    }
    // Phase 1b: prefix state (register-accumulated over prior chunks)
    {
        size_t sb = (size_t)nh * NCH * SROW;
        for (int idx = tid; idx < 128*64; idx += 512) {
            int f = idx >> 6, e = idx & 63;
            float a = 0.0f;
            for (int cp = 0; cp < c; cp++)
                a += g_S[sb + (size_t)cp * SROW + idx];
            sP[f*SVE + e] = a;
        }
        if (tid < 128) {
            float a = 0.0f;
            for (int cp = 0; cp < c; cp++)
                a += g_S[sb + (size_t)cp * SROW + 8192 + tid];
            sPden[tid] = a;
        }
    }
    __syncthreads();

    // Phase 2: scores = PhiQ^T(rows t) @ PhiK (cols t'), k = f (128)
    const int m2 = (wid & 3) * 32;
    const int n2 = (wid >> 2) * 32;
    float acc[2][4][4] = {};
#pragma unroll
    for (int k8 = 0; k8 < 16; k8++) {
        const int kk = k8 * 8 + tid4;
        uint32_t af[2][4];
#pragma unroll
        for (int mt = 0; mt < 2; mt++) {
            int r = m2 + mt * 16 + gid;
            af[mt][0] = f2tf(sQT[kk*SFT + r]);
            af[mt][1] = f2tf(sQT[kk*SFT + r + 8]);
            af[mt][2] = f2tf(sQT[(kk+4)*SFT + r]);
            af[mt][3] = f2tf(sQT[(kk+4)*SFT + r + 8]);
        }
        uint32_t bf[4][2];
#pragma unroll
        for (int nt = 0; nt < 4; nt++) {
            int nn = n2 + nt * 8 + gid;
            bf[nt][0] = f2tf(sKT[kk*SFT + nn]);
            bf[nt][1] = f2tf(sKT[(kk+4)*SFT + nn]);
        }
#pragma unroll
        for (int mt = 0; mt < 2; mt++)
#pragma unroll
            for (int nt = 0; nt < 4; nt++)
                mma_tf32(acc[mt][nt], af[mt], bf[nt]);
    }
    __syncthreads();   // all warps done reading sKT

    // Write causal-masked A row-major into sA (= sKT region), accumulate row sums
    float* sA = sKT;
#pragma unroll
    for (int mt = 0; mt < 2; mt++) {
        int r = m2 + mt * 16 + gid;
        float rs_lo = 0.0f, rs_hi = 0.0f;
#pragma unroll
        for (int nt = 0; nt < 4; nt++) {
            int cb = n2 + nt * 8 + tid4 * 2;
            float v0 = (cb     <= r)     ? acc[mt][nt][0] : 0.0f;
            float v1 = (cb + 1 <= r)     ? acc[mt][nt][1] : 0.0f;
            float v2 = (cb     <= r + 8) ? acc[mt][nt][2] : 0.0f;
            float v3 = (cb + 1 <= r + 8) ? acc[mt][nt][3] : 0.0f;
            *(float2*)&sA[r * SFT + cb]       = make_float2(v0, v1);
            *(float2*)&sA[(r + 8) * SFT + cb] = make_float2(v2, v3);
            rs_lo += v0 + v1;
            rs_hi += v2 + v3;
        }
        atomicAdd(&sDen[r], rs_lo);
        atomicAdd(&sDen[r + 8], rs_hi);
    }
    __syncthreads();

    // Phase 3: out = A@V + PhiQ^T@P  (128x64), warp tile 32x16
    const int m3 = (wid & 3) * 32;
    const int n3 = (wid >> 2) * 16;
    float o[2][2][4] = {};
    // term 1: k = t' (keys), A row-major sA, B = V[t'][e]
#pragma unroll
    for (int k8 = 0; k8 < 16; k8++) {
        const int kk = k8 * 8 + tid4;
        uint32_t af[2][4];
#pragma unroll
        for (int mt = 0; mt < 2; mt++) {
            int r = m3 + mt * 16 + gid;
            af[mt][0] = f2tf(sA[r * SFT + kk]);
            af[mt][1] = f2tf(sA[(r + 8) * SFT + kk]);
            af[mt][2] = f2tf(sA[r * SFT + kk + 4]);
            af[mt][3] = f2tf(sA[(r + 8) * SFT + kk + 4]);
        }
        uint32_t bf[2][2];
#pragma unroll
        for (int nt = 0; nt < 2; nt++) {
            int nn = n3 + nt * 8 + gid;
            bf[nt][0] = f2tf(sV[kk*SVE + nn]);
            bf[nt][1] = f2tf(sV[(kk+4)*SVE + nn]);
        }
#pragma unroll
        for (int mt = 0; mt < 2; mt++)
#pragma unroll
            for (int nt = 0; nt < 2; nt++)
                mma_tf32(o[mt][nt], af[mt], bf[nt]);
    }
    // term 2: k = f (features), A = sQT[f][t] k-major, B = P[f][e]
#pragma unroll
    for (int k8 = 0; k8 < 16; k8++) {
        const int kk = k8 * 8 + tid4;
        uint32_t af[2][4];
#pragma unroll
        for (int mt = 0; mt < 2; mt++) {
            int r = m3 + mt * 16 + gid;
            af[mt][0] = f2tf(sQT[kk*SFT + r]);
            af[mt][1] = f2tf(sQT[kk*SFT + r + 8]);
            af[mt][2] = f2tf(sQT[(kk+4)*SFT + r]);
            af[mt][3] = f2tf(sQT[(kk+4)*SFT + r + 8]);
        }
        uint32_t bf[2][2];
#pragma unroll
        for (int nt = 0; nt < 2; nt++) {
            int nn = n3 + nt * 8 + gid;
            bf[nt][0] = f2tf(sP[kk*SVE + nn]);
            bf[nt][1] = f2tf(sP[(kk+4)*SVE + nn]);
        }
#pragma unroll
        for (int mt = 0; mt < 2; mt++)
#pragma unroll
            for (int nt = 0; nt < 2; nt++)
                mma_tf32(o[mt][nt], af[mt], bf[nt]);
    }
    // den inter-chunk term: den[t] += sum_f sQT[f][t]*Pden[f]  (fp32, 4-way split)
    {
        int t = tid & 127, part = tid >> 7;
        float s = 0.0f;
        for (int f = part * 32; f < part * 32 + 32; f++)
            s += sQT[f*SFT + t] * sPden[f];
        atomicAdd(&sDen[t], s);
    }
    __syncthreads();

    // Phase 4: normalize + write (N, Lq, H*dh)
#pragma unroll
    for (int mt = 0; mt < 2; mt++) {
        int r = m3 + mt * 16 + gid;
        float inv_lo = 1.0f / sDen[r];
        float inv_hi = 1.0f / sDen[r + 8];
        int tg_lo = c * TCH + r;
        int tg_hi = tg_lo + 8;
#pragma unroll
        for (int nt = 0; nt < 2; nt++) {
            int e = n3 + nt * 8 + tid4 * 2;
            *(float2*)&out[((n << 10) + tg_lo) * DDIM + (h << 6) + e] =
                make_float2(o[mt][nt][0] * inv_lo, o[mt][nt][1] * inv_lo);
            *(float2*)&out[((n << 10) + tg_hi) * DDIM + (h << 6) + e] =
                make_float2(o[mt][nt][2] * inv_hi, o[mt][nt][3] * inv_hi);
        }
    }
}

// ---------------------------------------------------------------------------
extern "C" void kernel_launch(void* const* d_in, const int* in_sizes, int n_in,
                              void* d_out, int out_size) {
    const float* query = (const float*)d_in[0];
    const float* key   = (const float*)d_in[1];
    const float* Wq    = (const float*)d_in[2];
    const float* Wk    = (const float*)d_in[3];
    const float* Wv    = (const float*)d_in[4];
    const float* coeff = (const float*)d_in[5];
    const float* pw    = (const float*)d_in[6];
    const float* pb    = (const float*)d_in[7];
    float* out = (float*)d_out;

    cudaFuncSetAttribute(proj_mma_kernel,
                         cudaFuncAttributeMaxDynamicSharedMemorySize, 65536);
    cudaFuncSetAttribute(chunk_state_kernel,
                         cudaFuncAttributeMaxDynamicSharedMemorySize, 102400);
    cudaFuncSetAttribute(attn_out_kernel,
                         cudaFuncAttributeMaxDynamicSharedMemorySize, 205824);

    proj_mma_kernel<<<dim3(MROWS/128, DDIM/128, 3), 256, 65536>>>(query, key, Wq, Wk, Wv);
    chunk_state_kernel<<<dim3(NHH, NCH), 512, 102400>>>(pw);
    attn_out_kernel<<<dim3(NHH, NCH), 512, 205824>>>(pw, pb, coeff, out);
}

// round 5
// speedup vs baseline: 2.1924x; 1.1337x over previous
#include <cuda_runtime.h>
#include <math.h>
#include <stdint.h>

// Problem constants
#define NB   2
#define LSEQ 1024
#define HH   8
#define DHD  64
#define DDIM 512
#define TCH  128
#define NCH  8
#define NHH  16
#define MROWS (NB*LSEQ)    // 2048
#define SROW 8320          // per-chunk state: 128x64 S + 128 den

// Device scratch (no cudaMalloc allowed)
__device__ float g_Q[MROWS*DDIM];
__device__ float g_K[MROWS*DDIM];
__device__ float g_V[MROWS*DDIM];
__device__ float g_S[NHH*NCH*SROW];
// tf32-pre-rounded copies of inputs
__device__ float g_cq[MROWS*DDIM];
__device__ float g_ck[MROWS*DDIM];
__device__ float g_cWq[DDIM*DDIM];
__device__ float g_cWk[DDIM*DDIM];
__device__ float g_cWv[DDIM*DDIM];

__device__ __forceinline__ float softplus_f(float x) {
    return fmaxf(x, 0.0f) + log1pf(expf(-fabsf(x)));
}

// ---------------------------------------------------------------------------
// Primitives (compile clean for compute_103 baseline target)
// ---------------------------------------------------------------------------
__device__ __forceinline__ uint32_t smem_u32(const void* p) {
    uint32_t a;
    asm("{ .reg .u64 t; cvta.to.shared.u64 t, %1; cvt.u32.u64 %0, t; }"
        : "=r"(a) : "l"(p));
    return a;
}
#define CP_ASYNC16(dst, src) \
    asm volatile("cp.async.cg.shared.global [%0], [%1], 16;" :: "r"(dst), "l"(src))
#define CP_COMMIT()  asm volatile("cp.async.commit_group;" ::: "memory")
#define CP_WAIT(n)   asm volatile("cp.async.wait_group %0;" :: "n"(n) : "memory")

__device__ __forceinline__ void mma_tf32(float* d, const uint32_t* a, const uint32_t* b) {
    asm volatile(
        "mma.sync.aligned.m16n8k8.row.col.f32.tf32.tf32.f32 "
        "{%0,%1,%2,%3}, {%4,%5,%6,%7}, {%8,%9}, {%0,%1,%2,%3};"
        : "+f"(d[0]), "+f"(d[1]), "+f"(d[2]), "+f"(d[3])
        : "r"(a[0]), "r"(a[1]), "r"(a[2]), "r"(a[3]), "r"(b[0]), "r"(b[1]));
}
// round-to-nearest fp32 -> tf32 bits (low 13 mantissa bits zeroed), as float
__device__ __forceinline__ float f2tf_f(float x) {
    uint32_t r;
    asm("cvt.rna.tf32.f32 %0, %1;" : "=r"(r) : "f"(x));
    return __uint_as_float(r);
}
// swizzle for proj smem: k column xor'd by row&7 (units of 4 floats)
__device__ __forceinline__ int swz(int row, int k) { return k ^ ((row & 7) << 2); }

// Padded strides (==8 mod 32 -> column-pattern fragment LDS conflict-free)
#define SFT 136
#define SVE 72

// ---------------------------------------------------------------------------
// Kernel 0: round inputs to tf32 (rna) once.
// y: 0=query, 1=key, 2=Wq, 3=Wk, 4=Wv
// ---------------------------------------------------------------------------
__global__ __launch_bounds__(256) void conv_tf32_kernel(
        const float* __restrict__ query, const float* __restrict__ key,
        const float* __restrict__ Wq, const float* __restrict__ Wk,
        const float* __restrict__ Wv) {
    const int y = blockIdx.y;
    const float* src; float* dst; int n4;
    switch (y) {
        case 0: src = query; dst = g_cq;  n4 = MROWS*DDIM/4; break;
        case 1: src = key;   dst = g_ck;  n4 = MROWS*DDIM/4; break;
        case 2: src = Wq;    dst = g_cWq; n4 = DDIM*DDIM/4;  break;
        case 3: src = Wk;    dst = g_cWk; n4 = DDIM*DDIM/4;  break;
        default: src = Wv;   dst = g_cWv; n4 = DDIM*DDIM/4;  break;
    }
    int idx = blockIdx.x * 256 + threadIdx.x;
    if (idx < n4) {
        float4 v = ((const float4*)src)[idx];
        v.x = f2tf_f(v.x); v.y = f2tf_f(v.y);
        v.z = f2tf_f(v.z); v.w = f2tf_f(v.w);
        ((float4*)dst)[idx] = v;
    }
}

// ---------------------------------------------------------------------------
// Kernel G: projection GEMM via warp tf32 mma, 256 threads, 8 warps (64x32).
// Inputs pre-rounded -> raw-bit fragment loads, zero cvts in mainloop.
// ---------------------------------------------------------------------------
__global__ __launch_bounds__(256) void proj_mma_kernel() {
    extern __shared__ __align__(16) float sm[];
    float* sAbuf[2] = { sm, sm + 4096 };
    float* sBbuf[2] = { sm + 8192, sm + 12288 };

    const int which = blockIdx.z;
    const float* __restrict__ A = (which == 0) ? g_cq : g_ck;
    const float* __restrict__ B = (which == 0) ? g_cWq : (which == 1) ? g_cWk : g_cWv;
    float* __restrict__ out = (which == 0) ? g_Q : (which == 1) ? g_K : g_V;
    const int am0 = blockIdx.x * 128;
    const int bn0 = blockIdx.y * 128;

    const int tid = threadIdx.x;
    const int wid = tid >> 5, lane = tid & 31;
    const int gid = lane >> 2, tid4 = lane & 3;
    const int m0 = (wid & 1) * 64;
    const int n0 = (wid >> 1) * 32;

    float acc[4][4][4];
#pragma unroll
    for (int i = 0; i < 4; i++)
#pragma unroll
        for (int j = 0; j < 4; j++)
#pragma unroll
            for (int q = 0; q < 4; q++) acc[i][j][q] = 0.0f;

    auto issue_stage = [&](int kt, int buf) {
        const int k0 = kt * 32;
        uint32_t sa = smem_u32(sAbuf[buf]);
        uint32_t sb = smem_u32(sBbuf[buf]);
#pragma unroll
        for (int i = 0; i < 4; i++) {
            int f4 = tid + 256 * i;
            int row = f4 >> 3;
            int k4  = (f4 & 7) << 2;
            int soff = (row * 32 + swz(row, k4)) * 4;
            CP_ASYNC16(sa + soff, &A[(size_t)(am0 + row) * DDIM + k0 + k4]);
            CP_ASYNC16(sb + soff, &B[(size_t)(bn0 + row) * DDIM + k0 + k4]);
        }
        CP_COMMIT();
    };

    issue_stage(0, 0);

    for (int kt = 0; kt < 16; kt++) {
        const int buf = kt & 1;
        if (kt < 15) issue_stage(kt + 1, buf ^ 1);
        if (kt < 15) CP_WAIT(1); else CP_WAIT(0);
        __syncthreads();

        const uint32_t* sA32 = (const uint32_t*)sAbuf[buf];
        const uint32_t* sB32 = (const uint32_t*)sBbuf[buf];
#pragma unroll
        for (int k8 = 0; k8 < 4; k8++) {
            const int kk = k8 * 8 + tid4;
            uint32_t af[4][4];
#pragma unroll
            for (int mt = 0; mt < 4; mt++) {
                int r = m0 + mt * 16 + gid;
                af[mt][0] = sA32[r * 32 + swz(r, kk)];
                af[mt][1] = sA32[(r + 8) * 32 + swz(r + 8, kk)];
                af[mt][2] = sA32[r * 32 + swz(r, kk + 4)];
                af[mt][3] = sA32[(r + 8) * 32 + swz(r + 8, kk + 4)];
            }
            uint32_t bf[4][2];
#pragma unroll
            for (int nt = 0; nt < 4; nt++) {
                int nn = n0 + nt * 8 + gid;
                bf[nt][0] = sB32[nn * 32 + swz(nn, kk)];
                bf[nt][1] = sB32[nn * 32 + swz(nn, kk + 4)];
            }
#pragma unroll
            for (int mt = 0; mt < 4; mt++)
#pragma unroll
                for (int nt = 0; nt < 4; nt++)
                    mma_tf32(acc[mt][nt], af[mt], bf[nt]);
        }
        __syncthreads();
    }

    const bool act = (which < 2);
#pragma unroll
    for (int mt = 0; mt < 4; mt++) {
#pragma unroll
        for (int nt = 0; nt < 4; nt++) {
            int row = am0 + m0 + mt * 16 + gid;
            int col = bn0 + n0 + nt * 8 + tid4 * 2;
            float v0 = acc[mt][nt][0], v1 = acc[mt][nt][1];
            float v2 = acc[mt][nt][2], v3 = acc[mt][nt][3];
            if (act) {
                v0 = softplus_f(v0); v1 = softplus_f(v1);
                v2 = softplus_f(v2); v3 = softplus_f(v3);
            }
            *(float2*)&out[(size_t)row * DDIM + col] = make_float2(v0, v1);
            *(float2*)&out[(size_t)(row + 8) * DDIM + col] = make_float2(v2, v3);
        }
    }
}

// ---------------------------------------------------------------------------
// Kernel B: per-chunk KV state via warp mma. Chunks 0..6 only (7 unused).
// smem values pre-rounded at store; mainloop raw-bit LDS.
// ---------------------------------------------------------------------------
__global__ __launch_bounds__(512) void chunk_state_kernel(const float* __restrict__ pw) {
    extern __shared__ __align__(16) float smB[];
    float* sKf = smB;                // [t][f] stride SFT
    float* sV  = smB + 128*SFT;      // [t][e] stride SVE

    const int nh = blockIdx.x, c = blockIdx.y;
    const int n = nh >> 3, h = nh & 7;
    const int tid = threadIdx.x;
    const int wid = tid >> 5, lane = tid & 31;
    const int gid = lane >> 2, tid4 = lane & 3;

    for (int idx = tid; idx < 128*64; idx += 512) {
        int t = idx >> 6, di = idx & 63;
        int tg = c * TCH + t;
        int gbase = ((n << 10) + tg) * DDIM + (h << 6) + di;
        float kv = g_K[gbase];
        float vv = g_V[gbase];
        float w  = pw[(h << 6) + di];
        float s, cs;
        sincosf((float)tg * w, &s, &cs);
        sKf[t*SFT + di]      = f2tf_f(kv * cs);
        sKf[t*SFT + 64 + di] = f2tf_f(kv * s);
        sV[t*SVE + di]       = f2tf_f(vv);
    }
    __syncthreads();

    const uint32_t* sKf32 = (const uint32_t*)sKf;
    const uint32_t* sV32  = (const uint32_t*)sV;
    const int m0 = (wid & 3) * 32;
    const int n0 = (wid >> 2) * 16;
    float acc[2][2][4] = {};
#pragma unroll
    for (int k8 = 0; k8 < 16; k8++) {
        const int kk = k8 * 8 + tid4;
        uint32_t af[2][4];
#pragma unroll
        for (int mt = 0; mt < 2; mt++) {
            int r = m0 + mt * 16 + gid;
            af[mt][0] = sKf32[kk*SFT + r];
            af[mt][1] = sKf32[kk*SFT + r + 8];
            af[mt][2] = sKf32[(kk+4)*SFT + r];
            af[mt][3] = sKf32[(kk+4)*SFT + r + 8];
        }
        uint32_t bf[2][2];
#pragma unroll
        for (int nt = 0; nt < 2; nt++) {
            int nn = n0 + nt * 8 + gid;
            bf[nt][0] = sV32[kk*SVE + nn];
            bf[nt][1] = sV32[(kk+4)*SVE + nn];
        }
#pragma unroll
        for (int mt = 0; mt < 2; mt++)
#pragma unroll
            for (int nt = 0; nt < 2; nt++)
                mma_tf32(acc[mt][nt], af[mt], bf[nt]);
    }
    size_t base = (size_t)(nh * NCH + c) * SROW;
#pragma unroll
    for (int mt = 0; mt < 2; mt++) {
#pragma unroll
        for (int nt = 0; nt < 2; nt++) {
            int f = m0 + mt * 16 + gid;
            int e = n0 + nt * 8 + tid4 * 2;
            *(float2*)&g_S[base + (size_t)f * 64 + e] =
                make_float2(acc[mt][nt][0], acc[mt][nt][1]);
            *(float2*)&g_S[base + (size_t)(f + 8) * 64 + e] =
                make_float2(acc[mt][nt][2], acc[mt][nt][3]);
        }
    }
    if (tid < 128) {
        float s = 0.0f;
        for (int t = 0; t < 128; t++) s += sKf[t*SFT + tid];
        g_S[base + 8192 + tid] = s;
    }
}

// ---------------------------------------------------------------------------
// Kernel D: per-chunk output, all GEMMs raw-bit warp mma. 512 threads.
// smem floats (offsets):
//   sQT 0 (128xSFT) | sKT 17408 (128xSFT, reused as sAT col-major)
//   sV 34816 (128xSVE) | sP 44032 (128xSVE) | sPden 53248 | sDen 53376
//   sCB 53504 | sSB 53568   total 53632 floats = 214528 B
// ---------------------------------------------------------------------------
__global__ __launch_bounds__(512, 1) void attn_out_kernel(
        const float* __restrict__ pw, const float* __restrict__ pb,
        const float* __restrict__ coeff, float* __restrict__ out) {
    extern __shared__ __align__(16) float smD[];
    float* sQT   = smD;
    float* sKT   = smD + 17408;
    float* sV    = smD + 34816;
    float* sP    = smD + 44032;
    float* sPden = smD + 53248;
    float* sDen  = smD + 53376;
    float* sCB   = smD + 53504;
    float* sSB   = smD + 53568;

    const int nh = blockIdx.x, c = blockIdx.y;
    const int n = nh >> 3, h = nh & 7;
    const int tid = threadIdx.x;
    const int wid = tid >> 5, lane = tid & 31;
    const int gid = lane >> 2, tid4 = lane & 3;

    if (tid < 128) sDen[tid] = 0.0f;
    if (tid >= 128 && tid < 192) {
        int di = tid - 128;
        float sb_, cb_;
        sincosf(pb[(h << 6) + di], &sb_, &cb_);
        sCB[di] = cb_; sSB[di] = sb_;
    }
    __syncthreads();

    // Phase 1a: features + V (one accurate sincos per element + rotation)
    for (int idx = tid; idx < 128*64; idx += 512) {
        int t = idx >> 6, di = idx & 63;
        int tg = c * TCH + t;
        int gbase = ((n << 10) + tg) * DDIM + (h << 6) + di;
        float qv = g_Q[gbase], kv = g_K[gbase], vv = g_V[gbase];
        float w  = pw[(h << 6) + di];
        float cf = coeff[(h << 6) + di];
        float sk, ck;
        sincosf((float)tg * w, &sk, &ck);
        float cb_ = sCB[di], sb_ = sSB[di];
        float cq = ck * cb_ - sk * sb_;
        float sq = sk * cb_ + ck * sb_;
        float qc = qv * cf;
        sQT[di*SFT + t]        = f2tf_f(qc * cq);
        sQT[(64 + di)*SFT + t] = f2tf_f(qc * sq);
        sKT[di*SFT + t]        = f2tf_f(kv * ck);
        sKT[(64 + di)*SFT + t] = f2tf_f(kv * sk);
        sV[t*SVE + di]         = f2tf_f(vv);
    }
    // Phase 1b: prefix state (fp32 accumulate, round at store)
    {
        size_t sb = (size_t)nh * NCH * SROW;
        for (int idx = tid; idx < 128*64; idx += 512) {
            int f = idx >> 6, e = idx & 63;
            float a = 0.0f;
            for (int cp = 0; cp < c; cp++)
                a += g_S[sb + (size_t)cp * SROW + idx];
            sP[f*SVE + e] = f2tf_f(a);
        }
        if (tid < 128) {
            float a = 0.0f;
            for (int cp = 0; cp < c; cp++)
                a += g_S[sb + (size_t)cp * SROW + 8192 + tid];
            sPden[tid] = a;
        }
    }
    __syncthreads();

    const uint32_t* sQT32 = (const uint32_t*)sQT;
    const uint32_t* sKT32 = (const uint32_t*)sKT;
    const uint32_t* sV32  = (const uint32_t*)sV;
    const uint32_t* sP32  = (const uint32_t*)sP;

    // Phase 2: scores (128x128, k = feature 128)
    const int m2 = (wid & 3) * 32;
    const int n2 = (wid >> 2) * 32;
    float acc[2][4][4] = {};
#pragma unroll
    for (int k8 = 0; k8 < 16; k8++) {
        const int kk = k8 * 8 + tid4;
        uint32_t af[2][4];
#pragma unroll
        for (int mt = 0; mt < 2; mt++) {
            int r = m2 + mt * 16 + gid;
            af[mt][0] = sQT32[kk*SFT + r];
            af[mt][1] = sQT32[kk*SFT + r + 8];
            af[mt][2] = sQT32[(kk+4)*SFT + r];
            af[mt][3] = sQT32[(kk+4)*SFT + r + 8];
        }
        uint32_t bf[4][2];
#pragma unroll
        for (int nt = 0; nt < 4; nt++) {
            int nn = n2 + nt * 8 + gid;
            bf[nt][0] = sKT32[kk*SFT + nn];
            bf[nt][1] = sKT32[(kk+4)*SFT + nn];
        }
#pragma unroll
        for (int mt = 0; mt < 2; mt++)
#pragma unroll
            for (int nt = 0; nt < 4; nt++)
                mma_tf32(acc[mt][nt], af[mt], bf[nt]);
    }
    __syncthreads();   // all warps done reading sKT

    // Causal mask -> write transposed sAT[col][row] (round at store), row sums
    float* sAT = sKT;
#pragma unroll
    for (int mt = 0; mt < 2; mt++) {
        int r = m2 + mt * 16 + gid;
        float rs_lo = 0.0f, rs_hi = 0.0f;
#pragma unroll
        for (int nt = 0; nt < 4; nt++) {
            int cb = n2 + nt * 8 + tid4 * 2;
            float v0 = (cb     <= r)     ? acc[mt][nt][0] : 0.0f;
            float v1 = (cb + 1 <= r)     ? acc[mt][nt][1] : 0.0f;
            float v2 = (cb     <= r + 8) ? acc[mt][nt][2] : 0.0f;
            float v3 = (cb + 1 <= r + 8) ? acc[mt][nt][3] : 0.0f;
            sAT[cb * SFT + r]           = f2tf_f(v0);
            sAT[(cb + 1) * SFT + r]     = f2tf_f(v1);
            sAT[cb * SFT + r + 8]       = f2tf_f(v2);
            sAT[(cb + 1) * SFT + r + 8] = f2tf_f(v3);
            rs_lo += v0 + v1;
            rs_hi += v2 + v3;
        }
        atomicAdd(&sDen[r], rs_lo);
        atomicAdd(&sDen[r + 8], rs_hi);
    }
    __syncthreads();

    const uint32_t* sAT32 = (const uint32_t*)sAT;

    // Phase 3: out = A@V + PhiQ^T@P  (128x64), warp tile 32x16
    const int m3 = (wid & 3) * 32;
    const int n3 = (wid >> 2) * 16;
    float o[2][2][4] = {};
    // term 1: k = key index (A stored transposed -> column reads)
#pragma unroll
    for (int k8 = 0; k8 < 16; k8++) {
        const int kk = k8 * 8 + tid4;
        uint32_t af[2][4];
#pragma unroll
        for (int mt = 0; mt < 2; mt++) {
            int r = m3 + mt * 16 + gid;
            af[mt][0] = sAT32[kk*SFT + r];
            af[mt][1] = sAT32[kk*SFT + r + 8];
            af[mt][2] = sAT32[(kk+4)*SFT + r];
            af[mt][3] = sAT32[(kk+4)*SFT + r + 8];
        }
        uint32_t bf[2][2];
#pragma unroll
        for (int nt = 0; nt < 2; nt++) {
            int nn = n3 + nt * 8 + gid;
            bf[nt][0] = sV32[kk*SVE + nn];
            bf[nt][1] = sV32[(kk+4)*SVE + nn];
        }
#pragma unroll
        for (int mt = 0; mt < 2; mt++)
#pragma unroll
            for (int nt = 0; nt < 2; nt++)
                mma_tf32(o[mt][nt], af[mt], bf[nt]);
    }
    // term 2: k = feature
#pragma unroll
    for (int k8 = 0; k8 < 16; k8++) {
        const int kk = k8 * 8 + tid4;
        uint32_t af[2][4];
#pragma unroll
        for (int mt = 0; mt < 2; mt++) {
            int r = m3 + mt * 16 + gid;
            af[mt][0] = sQT32[kk*SFT + r];
            af[mt][1] = sQT32[kk*SFT + r + 8];
            af[mt][2] = sQT32[(kk+4)*SFT + r];
            af[mt][3] = sQT32[(kk+4)*SFT + r + 8];
        }
        uint32_t bf[2][2];
#pragma unroll
        for (int nt = 0; nt < 2; nt++) {
            int nn = n3 + nt * 8 + gid;
            bf[nt][0] = sP32[kk*SVE + nn];
            bf[nt][1] = sP32[(kk+4)*SVE + nn];
        }
#pragma unroll
        for (int mt = 0; mt < 2; mt++)
#pragma unroll
            for (int nt = 0; nt < 2; nt++)
                mma_tf32(o[mt][nt], af[mt], bf[nt]);
    }
    // den inter-chunk term (fp32, 4-way split over f)
    {
        int t = tid & 127, part = tid >> 7;
        float s = 0.0f;
        for (int f = part * 32; f < part * 32 + 32; f++)
            s += sQT[f*SFT + t] * sPden[f];
        atomicAdd(&sDen[t], s);
    }
    __syncthreads();

    // Phase 4: normalize + write (N, Lq, H*dh)
#pragma unroll
    for (int mt = 0; mt < 2; mt++) {
        int r = m3 + mt * 16 + gid;
        float inv_lo = 1.0f / sDen[r];
        float inv_hi = 1.0f / sDen[r + 8];
        int tg_lo = c * TCH + r;
        int tg_hi = tg_lo + 8;
#pragma unroll
        for (int nt = 0; nt < 2; nt++) {
            int e = n3 + nt * 8 + tid4 * 2;
            *(float2*)&out[((n << 10) + tg_lo) * DDIM + (h << 6) + e] =
                make_float2(o[mt][nt][0] * inv_lo, o[mt][nt][1] * inv_lo);
            *(float2*)&out[((n << 10) + tg_hi) * DDIM + (h << 6) + e] =
                make_float2(o[mt][nt][2] * inv_hi, o[mt][nt][3] * inv_hi);
        }
    }
}

// ---------------------------------------------------------------------------
extern "C" void kernel_launch(void* const* d_in, const int* in_sizes, int n_in,
                              void* d_out, int out_size) {
    const float* query = (const float*)d_in[0];
    const float* key   = (const float*)d_in[1];
    const float* Wq    = (const float*)d_in[2];
    const float* Wk    = (const float*)d_in[3];
    const float* Wv    = (const float*)d_in[4];
    const float* coeff = (const float*)d_in[5];
    const float* pw    = (const float*)d_in[6];
    const float* pb    = (const float*)d_in[7];
    float* out = (float*)d_out;

    cudaFuncSetAttribute(proj_mma_kernel,
                         cudaFuncAttributeMaxDynamicSharedMemorySize, 65536);
    cudaFuncSetAttribute(chunk_state_kernel,
                         cudaFuncAttributeMaxDynamicSharedMemorySize, 107520);
    cudaFuncSetAttribute(attn_out_kernel,
                         cudaFuncAttributeMaxDynamicSharedMemorySize, 214528);

    conv_tf32_kernel<<<dim3(1024, 5), 256>>>(query, key, Wq, Wk, Wv);
    proj_mma_kernel<<<dim3(MROWS/128, DDIM/128, 3), 256, 65536>>>();
    chunk_state_kernel<<<dim3(NHH, NCH-1), 512, 107520>>>(pw);
    attn_out_kernel<<<dim3(NHH, NCH), 512, 214528>>>(pw, pb, coeff, out);
}

// round 6
// speedup vs baseline: 2.2575x; 1.0297x over previous
#include <cuda_runtime.h>
#include <math.h>
#include <stdint.h>

// Problem constants
#define NB   2
#define LSEQ 1024
#define HH   8
#define DHD  64
#define DDIM 512
#define TCH  128
#define NCH  8
#define NHH  16
#define MROWS (NB*LSEQ)    // 2048
#define SROW 8320          // per-chunk state: 128x64 S + 128 den

// Device scratch (no cudaMalloc allowed)
__device__ float g_Q[MROWS*DDIM];
__device__ float g_K[MROWS*DDIM];
__device__ float g_V[MROWS*DDIM];
__device__ float g_S[NHH*NCH*SROW];
__device__ float g_SP[NHH*NCH*SROW];   // prefix (cumulative) states
// tf32-pre-rounded weights
__device__ float g_cWq[DDIM*DDIM];
__device__ float g_cWk[DDIM*DDIM];
__device__ float g_cWv[DDIM*DDIM];

__device__ __forceinline__ float softplus_f(float x) {
    return fmaxf(x, 0.0f) + log1pf(expf(-fabsf(x)));
}

// ---------------------------------------------------------------------------
// Primitives (compile clean for compute_103 baseline target)
// ---------------------------------------------------------------------------
__device__ __forceinline__ uint32_t smem_u32(const void* p) {
    uint32_t a;
    asm("{ .reg .u64 t; cvta.to.shared.u64 t, %1; cvt.u32.u64 %0, t; }"
        : "=r"(a) : "l"(p));
    return a;
}
#define CP_ASYNC16(dst, src) \
    asm volatile("cp.async.cg.shared.global [%0], [%1], 16;" :: "r"(dst), "l"(src))
#define CP_COMMIT()  asm volatile("cp.async.commit_group;" ::: "memory")
#define CP_WAIT(n)   asm volatile("cp.async.wait_group %0;" :: "n"(n) : "memory")

__device__ __forceinline__ void mma_tf32(float* d, const uint32_t* a, const uint32_t* b) {
    asm volatile(
        "mma.sync.aligned.m16n8k8.row.col.f32.tf32.tf32.f32 "
        "{%0,%1,%2,%3}, {%4,%5,%6,%7}, {%8,%9}, {%0,%1,%2,%3};"
        : "+f"(d[0]), "+f"(d[1]), "+f"(d[2]), "+f"(d[3])
        : "r"(a[0]), "r"(a[1]), "r"(a[2]), "r"(a[3]), "r"(b[0]), "r"(b[1]));
}
// round-to-nearest fp32 -> tf32 bits, returned as float bit-pattern
__device__ __forceinline__ float f2tf_f(float x) {
    uint32_t r;
    asm("cvt.rna.tf32.f32 %0, %1;" : "=r"(r) : "f"(x));
    return __uint_as_float(r);
}
// swizzle for proj smem: k column xor'd by row&7 (units of 4 floats)
__device__ __forceinline__ int swz(int row, int k) { return k ^ ((row & 7) << 2); }

// Padded strides (==8 mod 32 -> column-pattern fragment LDS conflict-free)
#define SFT 136
#define SVE 72

// ---------------------------------------------------------------------------
// Kernel 0: round weights to tf32 (rna) once. y: 0=Wq, 1=Wk, 2=Wv
// ---------------------------------------------------------------------------
__global__ __launch_bounds__(256) void conv_tf32_kernel(
        const float* __restrict__ Wq, const float* __restrict__ Wk,
        const float* __restrict__ Wv) {
    const int y = blockIdx.y;
    const float* src = (y == 0) ? Wq : (y == 1) ? Wk : Wv;
    float* dst = (y == 0) ? g_cWq : (y == 1) ? g_cWk : g_cWv;
    int idx = blockIdx.x * 256 + threadIdx.x;
    if (idx < DDIM*DDIM/4) {
        float4 v = ((const float4*)src)[idx];
        v.x = f2tf_f(v.x); v.y = f2tf_f(v.y);
        v.z = f2tf_f(v.z); v.w = f2tf_f(v.w);
        ((float4*)dst)[idx] = v;
    }
}

// ---------------------------------------------------------------------------
// Kernel G: projection GEMM, warp tf32 mma. Block tile 128x64, 8 warps
// (warp 32x32), BK=32 double-buffered cp.async -> 49KB smem, ~70 regs
// => 3 blocks/SM (24 warps). A = raw fp32 (HW truncation), B = pre-rounded.
// ---------------------------------------------------------------------------
__global__ __launch_bounds__(256) void proj_mma_kernel(
        const float* __restrict__ query, const float* __restrict__ key) {
    extern __shared__ __align__(16) float sm[];
    float* sAbuf[2] = { sm, sm + 4096 };          // 128 x 32
    float* sBbuf[2] = { sm + 8192, sm + 10240 };  // 64 x 32

    const int which = blockIdx.z;
    const float* __restrict__ A = (which == 0) ? query : key;
    const float* __restrict__ B = (which == 0) ? g_cWq : (which == 1) ? g_cWk : g_cWv;
    float* __restrict__ out = (which == 0) ? g_Q : (which == 1) ? g_K : g_V;
    const int am0 = blockIdx.x * 128;
    const int bn0 = blockIdx.y * 64;

    const int tid = threadIdx.x;
    const int wid = tid >> 5, lane = tid & 31;
    const int gid = lane >> 2, tid4 = lane & 3;
    const int m0 = (wid & 3) * 32;
    const int n0 = (wid >> 2) * 32;

    float acc[2][4][4];
#pragma unroll
    for (int i = 0; i < 2; i++)
#pragma unroll
        for (int j = 0; j < 4; j++)
#pragma unroll
            for (int q = 0; q < 4; q++) acc[i][j][q] = 0.0f;

    auto issue_stage = [&](int kt, int buf) {
        const int k0 = kt * 32;
        uint32_t sa = smem_u32(sAbuf[buf]);
        uint32_t sb = smem_u32(sBbuf[buf]);
#pragma unroll
        for (int i = 0; i < 4; i++) {
            int f4 = tid + 256 * i;
            int row = f4 >> 3;
            int k4  = (f4 & 7) << 2;
            int soff = (row * 32 + swz(row, k4)) * 4;
            CP_ASYNC16(sa + soff, &A[(size_t)(am0 + row) * DDIM + k0 + k4]);
        }
#pragma unroll
        for (int i = 0; i < 2; i++) {
            int f4 = tid + 256 * i;
            int row = f4 >> 3;
            int k4  = (f4 & 7) << 2;
            int soff = (row * 32 + swz(row, k4)) * 4;
            CP_ASYNC16(sb + soff, &B[(size_t)(bn0 + row) * DDIM + k0 + k4]);
        }
        CP_COMMIT();
    };

    issue_stage(0, 0);

    for (int kt = 0; kt < 16; kt++) {
        const int buf = kt & 1;
        if (kt < 15) issue_stage(kt + 1, buf ^ 1);
        if (kt < 15) CP_WAIT(1); else CP_WAIT(0);
        __syncthreads();

        const uint32_t* sA32 = (const uint32_t*)sAbuf[buf];
        const uint32_t* sB32 = (const uint32_t*)sBbuf[buf];
#pragma unroll
        for (int k8 = 0; k8 < 4; k8++) {
            const int kk = k8 * 8 + tid4;
            uint32_t af[2][4];
#pragma unroll
            for (int mt = 0; mt < 2; mt++) {
                int r = m0 + mt * 16 + gid;
                af[mt][0] = sA32[r * 32 + swz(r, kk)];
                af[mt][1] = sA32[(r + 8) * 32 + swz(r + 8, kk)];
                af[mt][2] = sA32[r * 32 + swz(r, kk + 4)];
                af[mt][3] = sA32[(r + 8) * 32 + swz(r + 8, kk + 4)];
            }
            uint32_t bf[4][2];
#pragma unroll
            for (int nt = 0; nt < 4; nt++) {
                int nn = n0 + nt * 8 + gid;
                bf[nt][0] = sB32[nn * 32 + swz(nn, kk)];
                bf[nt][1] = sB32[nn * 32 + swz(nn, kk + 4)];
            }
#pragma unroll
            for (int mt = 0; mt < 2; mt++)
#pragma unroll
                for (int nt = 0; nt < 4; nt++)
                    mma_tf32(acc[mt][nt], af[mt], bf[nt]);
        }
        __syncthreads();
    }

    const bool act = (which < 2);
#pragma unroll
    for (int mt = 0; mt < 2; mt++) {
#pragma unroll
        for (int nt = 0; nt < 4; nt++) {
            int row = am0 + m0 + mt * 16 + gid;
            int col = bn0 + n0 + nt * 8 + tid4 * 2;
            float v0 = acc[mt][nt][0], v1 = acc[mt][nt][1];
            float v2 = acc[mt][nt][2], v3 = acc[mt][nt][3];
            if (act) {
                v0 = softplus_f(v0); v1 = softplus_f(v1);
                v2 = softplus_f(v2); v3 = softplus_f(v3);
            }
            *(float2*)&out[(size_t)row * DDIM + col] = make_float2(v0, v1);
            *(float2*)&out[(size_t)(row + 8) * DDIM + col] = make_float2(v2, v3);
        }
    }
}

// ---------------------------------------------------------------------------
// Kernel B: per-chunk KV state via warp mma. Chunks 0..6 only (7 unused).
// ---------------------------------------------------------------------------
__global__ __launch_bounds__(512) void chunk_state_kernel(const float* __restrict__ pw) {
    extern __shared__ __align__(16) float smB[];
    float* sKf = smB;                // [t][f] stride SFT
    float* sV  = smB + 128*SFT;      // [t][e] stride SVE

    const int nh = blockIdx.x, c = blockIdx.y;
    const int n = nh >> 3, h = nh & 7;
    const int tid = threadIdx.x;
    const int wid = tid >> 5, lane = tid & 31;
    const int gid = lane >> 2, tid4 = lane & 3;

    for (int idx = tid; idx < 128*64; idx += 512) {
        int t = idx >> 6, di = idx & 63;
        int tg = c * TCH + t;
        int gbase = ((n << 10) + tg) * DDIM + (h << 6) + di;
        float kv = g_K[gbase];
        float vv = g_V[gbase];
        float w  = pw[(h << 6) + di];
        float s, cs;
        sincosf((float)tg * w, &s, &cs);
        sKf[t*SFT + di]      = f2tf_f(kv * cs);
        sKf[t*SFT + 64 + di] = f2tf_f(kv * s);
        sV[t*SVE + di]       = f2tf_f(vv);
    }
    __syncthreads();

    const uint32_t* sKf32 = (const uint32_t*)sKf;
    const uint32_t* sV32  = (const uint32_t*)sV;
    const int m0 = (wid & 3) * 32;
    const int n0 = (wid >> 2) * 16;
    float acc[2][2][4] = {};
#pragma unroll
    for (int k8 = 0; k8 < 16; k8++) {
        const int kk = k8 * 8 + tid4;
        uint32_t af[2][4];
#pragma unroll
        for (int mt = 0; mt < 2; mt++) {
            int r = m0 + mt * 16 + gid;
            af[mt][0] = sKf32[kk*SFT + r];
            af[mt][1] = sKf32[kk*SFT + r + 8];
            af[mt][2] = sKf32[(kk+4)*SFT + r];
            af[mt][3] = sKf32[(kk+4)*SFT + r + 8];
        }
        uint32_t bf[2][2];
#pragma unroll
        for (int nt = 0; nt < 2; nt++) {
            int nn = n0 + nt * 8 + gid;
            bf[nt][0] = sV32[kk*SVE + nn];
            bf[nt][1] = sV32[(kk+4)*SVE + nn];
        }
#pragma unroll
        for (int mt = 0; mt < 2; mt++)
#pragma unroll
            for (int nt = 0; nt < 2; nt++)
                mma_tf32(acc[mt][nt], af[mt], bf[nt]);
    }
    size_t base = (size_t)(nh * NCH + c) * SROW;
#pragma unroll
    for (int mt = 0; mt < 2; mt++) {
#pragma unroll
        for (int nt = 0; nt < 2; nt++) {
            int f = m0 + mt * 16 + gid;
            int e = n0 + nt * 8 + tid4 * 2;
            *(float2*)&g_S[base + (size_t)f * 64 + e] =
                make_float2(acc[mt][nt][0], acc[mt][nt][1]);
            *(float2*)&g_S[base + (size_t)(f + 8) * 64 + e] =
                make_float2(acc[mt][nt][2], acc[mt][nt][3]);
        }
    }
    if (tid < 128) {
        float s = 0.0f;
        for (int t = 0; t < 128; t++) s += sKf[t*SFT + tid];
        g_S[base + 8192 + tid] = s;
    }
}

// ---------------------------------------------------------------------------
// Kernel C: prefix scan of chunk states. g_SP[c] = sum_{cp<c} g_S[cp].
// ---------------------------------------------------------------------------
__global__ __launch_bounds__(256) void scan_state_kernel() {
    const int nh = blockIdx.x, part = blockIdx.y;   // 8 parts of 1040
    const size_t base = (size_t)nh * NCH * SROW;
    const int lo = part * 1040;
    const int hi = (lo + 1040 < SROW) ? lo + 1040 : SROW;
    for (int idx = lo + threadIdx.x; idx < hi; idx += 256) {
        float run = 0.0f;
#pragma unroll
        for (int c = 1; c < NCH; c++) {
            run += g_S[base + (size_t)(c - 1) * SROW + idx];
            g_SP[base + (size_t)c * SROW + idx] = run;
        }
    }
}

// ---------------------------------------------------------------------------
// Kernel D: per-chunk output, all GEMMs raw-bit warp mma. 512 threads.
// ---------------------------------------------------------------------------
__global__ __launch_bounds__(512, 1) void attn_out_kernel(
        const float* __restrict__ pw, const float* __restrict__ pb,
        const float* __restrict__ coeff, float* __restrict__ out) {
    extern __shared__ __align__(16) float smD[];
    float* sQT   = smD;
    float* sKT   = smD + 17408;
    float* sV    = smD + 34816;
    float* sP    = smD + 44032;
    float* sPden = smD + 53248;
    float* sDen  = smD + 53376;
    float* sCB   = smD + 53504;
    float* sSB   = smD + 53568;

    const int nh = blockIdx.x, c = blockIdx.y;
    const int n = nh >> 3, h = nh & 7;
    const int tid = threadIdx.x;
    const int wid = tid >> 5, lane = tid & 31;
    const int gid = lane >> 2, tid4 = lane & 3;

    if (tid < 128) sDen[tid] = 0.0f;
    if (tid >= 128 && tid < 192) {
        int di = tid - 128;
        float sb_, cb_;
        sincosf(pb[(h << 6) + di], &sb_, &cb_);
        sCB[di] = cb_; sSB[di] = sb_;
    }
    __syncthreads();

    // Phase 1a: features + V (one accurate sincos per element + rotation)
    for (int idx = tid; idx < 128*64; idx += 512) {
        int t = idx >> 6, di = idx & 63;
        int tg = c * TCH + t;
        int gbase = ((n << 10) + tg) * DDIM + (h << 6) + di;
        float qv = g_Q[gbase], kv = g_K[gbase], vv = g_V[gbase];
        float w  = pw[(h << 6) + di];
        float cf = coeff[(h << 6) + di];
        float sk, ck;
        sincosf((float)tg * w, &sk, &ck);
        float cb_ = sCB[di], sb_ = sSB[di];
        float cq = ck * cb_ - sk * sb_;
        float sq = sk * cb_ + ck * sb_;
        float qc = qv * cf;
        sQT[di*SFT + t]        = f2tf_f(qc * cq);
        sQT[(64 + di)*SFT + t] = f2tf_f(qc * sq);
        sKT[di*SFT + t]        = f2tf_f(kv * ck);
        sKT[(64 + di)*SFT + t] = f2tf_f(kv * sk);
        sV[t*SVE + di]         = f2tf_f(vv);
    }
    // Phase 1b: prefix state (single coalesced read of cumulative state)
    if (c > 0) {
        size_t base = ((size_t)nh * NCH + c) * SROW;
        for (int idx = tid; idx < 128*64; idx += 512) {
            int f = idx >> 6, e = idx & 63;
            sP[f*SVE + e] = f2tf_f(g_SP[base + idx]);
        }
        if (tid < 128) sPden[tid] = g_SP[base + 8192 + tid];
    }
    __syncthreads();

    const uint32_t* sQT32 = (const uint32_t*)sQT;
    const uint32_t* sKT32 = (const uint32_t*)sKT;
    const uint32_t* sV32  = (const uint32_t*)sV;
    const uint32_t* sP32  = (const uint32_t*)sP;

    // Phase 2: scores (128x128, k = feature 128)
    const int m2 = (wid & 3) * 32;
    const int n2 = (wid >> 2) * 32;
    float acc[2][4][4] = {};
#pragma unroll
    for (int k8 = 0; k8 < 16; k8++) {
        const int kk = k8 * 8 + tid4;
        uint32_t af[2][4];
#pragma unroll
        for (int mt = 0; mt < 2; mt++) {
            int r = m2 + mt * 16 + gid;
            af[mt][0] = sQT32[kk*SFT + r];
            af[mt][1] = sQT32[kk*SFT + r + 8];
            af[mt][2] = sQT32[(kk+4)*SFT + r];
            af[mt][3] = sQT32[(kk+4)*SFT + r + 8];
        }
        uint32_t bf[4][2];
#pragma unroll
        for (int nt = 0; nt < 4; nt++) {
            int nn = n2 + nt * 8 + gid;
            bf[nt][0] = sKT32[kk*SFT + nn];
            bf[nt][1] = sKT32[(kk+4)*SFT + nn];
        }
#pragma unroll
        for (int mt = 0; mt < 2; mt++)
#pragma unroll
            for (int nt = 0; nt < 4; nt++)
                mma_tf32(acc[mt][nt], af[mt], bf[nt]);
    }
    __syncthreads();   // all warps done reading sKT

    // Causal mask -> write transposed sAT[col][row] (round at store), row sums
    float* sAT = sKT;
#pragma unroll
    for (int mt = 0; mt < 2; mt++) {
        int r = m2 + mt * 16 + gid;
        float rs_lo = 0.0f, rs_hi = 0.0f;
#pragma unroll
        for (int nt = 0; nt < 4; nt++) {
            int cb = n2 + nt * 8 + tid4 * 2;
            float v0 = (cb     <= r)     ? acc[mt][nt][0] : 0.0f;
            float v1 = (cb + 1 <= r)     ? acc[mt][nt][1] : 0.0f;
            float v2 = (cb     <= r + 8) ? acc[mt][nt][2] : 0.0f;
            float v3 = (cb + 1 <= r + 8) ? acc[mt][nt][3] : 0.0f;
            sAT[cb * SFT + r]           = f2tf_f(v0);
            sAT[(cb + 1) * SFT + r]     = f2tf_f(v1);
            sAT[cb * SFT + r + 8]       = f2tf_f(v2);
            sAT[(cb + 1) * SFT + r + 8] = f2tf_f(v3);
            rs_lo += v0 + v1;
            rs_hi += v2 + v3;
        }
        atomicAdd(&sDen[r], rs_lo);
        atomicAdd(&sDen[r + 8], rs_hi);
    }
    __syncthreads();

    const uint32_t* sAT32 = (const uint32_t*)sAT;

    // Phase 3: out = A@V + PhiQ^T@P  (128x64), warp tile 32x16
    const int m3 = (wid & 3) * 32;
    const int n3 = (wid >> 2) * 16;
    float o[2][2][4] = {};
    // term 1: k = key index (A stored transposed -> column reads)
#pragma unroll
    for (int k8 = 0; k8 < 16; k8++) {
        const int kk = k8 * 8 + tid4;
        uint32_t af[2][4];
#pragma unroll
        for (int mt = 0; mt < 2; mt++) {
            int r = m3 + mt * 16 + gid;
            af[mt][0] = sAT32[kk*SFT + r];
            af[mt][1] = sAT32[kk*SFT + r + 8];
            af[mt][2] = sAT32[(kk+4)*SFT + r];
            af[mt][3] = sAT32[(kk+4)*SFT + r + 8];
        }
        uint32_t bf[2][2];
#pragma unroll
        for (int nt = 0; nt < 2; nt++) {
            int nn = n3 + nt * 8 + gid;
            bf[nt][0] = sV32[kk*SVE + nn];
            bf[nt][1] = sV32[(kk+4)*SVE + nn];
        }
#pragma unroll
        for (int mt = 0; mt < 2; mt++)
#pragma unroll
            for (int nt = 0; nt < 2; nt++)
                mma_tf32(o[mt][nt], af[mt], bf[nt]);
    }
    if (c > 0) {
        // term 2: k = feature
#pragma unroll
        for (int k8 = 0; k8 < 16; k8++) {
            const int kk = k8 * 8 + tid4;
            uint32_t af[2][4];
#pragma unroll
            for (int mt = 0; mt < 2; mt++) {
                int r = m3 + mt * 16 + gid;
                af[mt][0] = sQT32[kk*SFT + r];
                af[mt][1] = sQT32[kk*SFT + r + 8];
                af[mt][2] = sQT32[(kk+4)*SFT + r];
                af[mt][3] = sQT32[(kk+4)*SFT + r + 8];
            }
            uint32_t bf[2][2];
#pragma unroll
            for (int nt = 0; nt < 2; nt++) {
                int nn = n3 + nt * 8 + gid;
                bf[nt][0] = sP32[kk*SVE + nn];
                bf[nt][1] = sP32[(kk+4)*SVE + nn];
            }
#pragma unroll
            for (int mt = 0; mt < 2; mt++)
#pragma unroll
                for (int nt = 0; nt < 2; nt++)
                    mma_tf32(o[mt][nt], af[mt], bf[nt]);
        }
        // den inter-chunk term (fp32, 4-way split over f)
        int t = tid & 127, part = tid >> 7;
        float s = 0.0f;
        for (int f = part * 32; f < part * 32 + 32; f++)
            s += sQT[f*SFT + t] * sPden[f];
        atomicAdd(&sDen[t], s);
    }
    __syncthreads();

    // Phase 4: normalize + write (N, Lq, H*dh)
#pragma unroll
    for (int mt = 0; mt < 2; mt++) {
        int r = m3 + mt * 16 + gid;
        float inv_lo = 1.0f / sDen[r];
        float inv_hi = 1.0f / sDen[r + 8];
        int tg_lo = c * TCH + r;
        int tg_hi = tg_lo + 8;
#pragma unroll
        for (int nt = 0; nt < 2; nt++) {
            int e = n3 + nt * 8 + tid4 * 2;
            *(float2*)&out[((n << 10) + tg_lo) * DDIM + (h << 6) + e] =
                make_float2(o[mt][nt][0] * inv_lo, o[mt][nt][1] * inv_lo);
            *(float2*)&out[((n << 10) + tg_hi) * DDIM + (h << 6) + e] =
                make_float2(o[mt][nt][2] * inv_hi, o[mt][nt][3] * inv_hi);
        }
    }
}

// ---------------------------------------------------------------------------
extern "C" void kernel_launch(void* const* d_in, const int* in_sizes, int n_in,
                              void* d_out, int out_size) {
    const float* query = (const float*)d_in[0];
    const float* key   = (const float*)d_in[1];
    const float* Wq    = (const float*)d_in[2];
    const float* Wk    = (const float*)d_in[3];
    const float* Wv    = (const float*)d_in[4];
    const float* coeff = (const float*)d_in[5];
    const float* pw    = (const float*)d_in[6];
    const float* pb    = (const float*)d_in[7];
    float* out = (float*)d_out;

    cudaFuncSetAttribute(proj_mma_kernel,
                         cudaFuncAttributeMaxDynamicSharedMemorySize, 49152);
    cudaFuncSetAttribute(chunk_state_kernel,
                         cudaFuncAttributeMaxDynamicSharedMemorySize, 107520);
    cudaFuncSetAttribute(attn_out_kernel,
                         cudaFuncAttributeMaxDynamicSharedMemorySize, 214528);

    conv_tf32_kernel<<<dim3(DDIM*DDIM/4/256, 3), 256>>>(Wq, Wk, Wv);
    proj_mma_kernel<<<dim3(MROWS/128, DDIM/64, 3), 256, 49152>>>(query, key);
    chunk_state_kernel<<<dim3(NHH, NCH-1), 512, 107520>>>(pw);
    scan_state_kernel<<<dim3(NHH, 8), 256>>>();
    attn_out_kernel<<<dim3(NHH, NCH), 512, 214528>>>(pw, pb, coeff, out);
}

// round 7
// speedup vs baseline: 2.4424x; 1.0819x over previous
#include <cuda_runtime.h>
#include <math.h>
#include <stdint.h>

// Problem constants
#define NB   2
#define LSEQ 1024
#define HH   8
#define DHD  64
#define DDIM 512
#define TCH  128
#define NCH  8
#define NHH  16
#define MROWS (NB*LSEQ)    // 2048
#define SROW 8320          // per-chunk state: 128x64 S + 128 den

// Device scratch (no cudaMalloc allowed)
__device__ float g_Q[MROWS*DDIM];
__device__ float g_K[MROWS*DDIM];
__device__ float g_V[MROWS*DDIM];
__device__ float g_S[NHH*NCH*SROW];
__device__ float g_SP[NHH*NCH*SROW];   // prefix (cumulative) states
// tf32-pre-rounded weights
__device__ float g_cWq[DDIM*DDIM];
__device__ float g_cWk[DDIM*DDIM];
__device__ float g_cWv[DDIM*DDIM];

__device__ __forceinline__ float softplus_f(float x) {
    return fmaxf(x, 0.0f) + log1pf(expf(-fabsf(x)));
}

// ---------------------------------------------------------------------------
// Primitives (compile clean for compute_103 baseline target)
// ---------------------------------------------------------------------------
__device__ __forceinline__ uint32_t smem_u32(const void* p) {
    uint32_t a;
    asm("{ .reg .u64 t; cvta.to.shared.u64 t, %1; cvt.u32.u64 %0, t; }"
        : "=r"(a) : "l"(p));
    return a;
}
#define CP_ASYNC16(dst, src) \
    asm volatile("cp.async.cg.shared.global [%0], [%1], 16;" :: "r"(dst), "l"(src))
#define CP_COMMIT()  asm volatile("cp.async.commit_group;" ::: "memory")
#define CP_WAIT(n)   asm volatile("cp.async.wait_group %0;" :: "n"(n) : "memory")

__device__ __forceinline__ void mma_tf32(float* d, const uint32_t* a, const uint32_t* b) {
    asm volatile(
        "mma.sync.aligned.m16n8k8.row.col.f32.tf32.tf32.f32 "
        "{%0,%1,%2,%3}, {%4,%5,%6,%7}, {%8,%9}, {%0,%1,%2,%3};"
        : "+f"(d[0]), "+f"(d[1]), "+f"(d[2]), "+f"(d[3])
        : "r"(a[0]), "r"(a[1]), "r"(a[2]), "r"(a[3]), "r"(b[0]), "r"(b[1]));
}
// round-to-nearest fp32 -> tf32 bits, returned as float bit-pattern
__device__ __forceinline__ float f2tf_f(float x) {
    uint32_t r;
    asm("cvt.rna.tf32.f32 %0, %1;" : "=r"(r) : "f"(x));
    return __uint_as_float(r);
}
// swizzle for proj smem: k column xor'd by row&7 (units of 4 floats)
__device__ __forceinline__ int swz(int row, int k) { return k ^ ((row & 7) << 2); }

// Padded strides (==8 mod 32 -> column-pattern fragment LDS conflict-free)
#define SFT 136
#define SVE 72

// ---------------------------------------------------------------------------
// Kernel 0: round weights to tf32 (rna) once. y: 0=Wq, 1=Wk, 2=Wv
// ---------------------------------------------------------------------------
__global__ __launch_bounds__(256) void conv_tf32_kernel(
        const float* __restrict__ Wq, const float* __restrict__ Wk,
        const float* __restrict__ Wv) {
    const int y = blockIdx.y;
    const float* src = (y == 0) ? Wq : (y == 1) ? Wk : Wv;
    float* dst = (y == 0) ? g_cWq : (y == 1) ? g_cWk : g_cWv;
    int idx = blockIdx.x * 256 + threadIdx.x;
    if (idx < DDIM*DDIM/4) {
        float4 v = ((const float4*)src)[idx];
        v.x = f2tf_f(v.x); v.y = f2tf_f(v.y);
        v.z = f2tf_f(v.z); v.w = f2tf_f(v.w);
        ((float4*)dst)[idx] = v;
    }
}

// ---------------------------------------------------------------------------
// Kernel G: projection GEMM, warp tf32 mma. Block tile 128x64, 8 warps
// (warp 32x32), BK=32 double-buffered cp.async -> 49KB smem.
// A = raw fp32 (HW truncation), B = pre-rounded.
// ---------------------------------------------------------------------------
__global__ __launch_bounds__(256) void proj_mma_kernel(
        const float* __restrict__ query, const float* __restrict__ key) {
    extern __shared__ __align__(16) float sm[];
    float* sAbuf[2] = { sm, sm + 4096 };          // 128 x 32
    float* sBbuf[2] = { sm + 8192, sm + 10240 };  // 64 x 32

    const int which = blockIdx.z;
    const float* __restrict__ A = (which == 0) ? query : key;
    const float* __restrict__ B = (which == 0) ? g_cWq : (which == 1) ? g_cWk : g_cWv;
    float* __restrict__ out = (which == 0) ? g_Q : (which == 1) ? g_K : g_V;
    const int am0 = blockIdx.x * 128;
    const int bn0 = blockIdx.y * 64;

    const int tid = threadIdx.x;
    const int wid = tid >> 5, lane = tid & 31;
    const int gid = lane >> 2, tid4 = lane & 3;
    const int m0 = (wid & 3) * 32;
    const int n0 = (wid >> 2) * 32;

    float acc[2][4][4];
#pragma unroll
    for (int i = 0; i < 2; i++)
#pragma unroll
        for (int j = 0; j < 4; j++)
#pragma unroll
            for (int q = 0; q < 4; q++) acc[i][j][q] = 0.0f;

    auto issue_stage = [&](int kt, int buf) {
        const int k0 = kt * 32;
        uint32_t sa = smem_u32(sAbuf[buf]);
        uint32_t sb = smem_u32(sBbuf[buf]);
#pragma unroll
        for (int i = 0; i < 4; i++) {
            int f4 = tid + 256 * i;
            int row = f4 >> 3;
            int k4  = (f4 & 7) << 2;
            int soff = (row * 32 + swz(row, k4)) * 4;
            CP_ASYNC16(sa + soff, &A[(size_t)(am0 + row) * DDIM + k0 + k4]);
        }
#pragma unroll
        for (int i = 0; i < 2; i++) {
            int f4 = tid + 256 * i;
            int row = f4 >> 3;
            int k4  = (f4 & 7) << 2;
            int soff = (row * 32 + swz(row, k4)) * 4;
            CP_ASYNC16(sb + soff, &B[(size_t)(bn0 + row) * DDIM + k0 + k4]);
        }
        CP_COMMIT();
    };

    issue_stage(0, 0);

    for (int kt = 0; kt < 16; kt++) {
        const int buf = kt & 1;
        if (kt < 15) issue_stage(kt + 1, buf ^ 1);
        if (kt < 15) CP_WAIT(1); else CP_WAIT(0);
        __syncthreads();

        const uint32_t* sA32 = (const uint32_t*)sAbuf[buf];
        const uint32_t* sB32 = (const uint32_t*)sBbuf[buf];
#pragma unroll
        for (int k8 = 0; k8 < 4; k8++) {
            const int kk = k8 * 8 + tid4;
            uint32_t af[2][4];
#pragma unroll
            for (int mt = 0; mt < 2; mt++) {
                int r = m0 + mt * 16 + gid;
                af[mt][0] = sA32[r * 32 + swz(r, kk)];
                af[mt][1] = sA32[(r + 8) * 32 + swz(r + 8, kk)];
                af[mt][2] = sA32[r * 32 + swz(r, kk + 4)];
                af[mt][3] = sA32[(r + 8) * 32 + swz(r + 8, kk + 4)];
            }
            uint32_t bf[4][2];
#pragma unroll
            for (int nt = 0; nt < 4; nt++) {
                int nn = n0 + nt * 8 + gid;
                bf[nt][0] = sB32[nn * 32 + swz(nn, kk)];
                bf[nt][1] = sB32[nn * 32 + swz(nn, kk + 4)];
            }
#pragma unroll
            for (int mt = 0; mt < 2; mt++)
#pragma unroll
                for (int nt = 0; nt < 4; nt++)
                    mma_tf32(acc[mt][nt], af[mt], bf[nt]);
        }
        __syncthreads();
    }

    const bool act = (which < 2);
#pragma unroll
    for (int mt = 0; mt < 2; mt++) {
#pragma unroll
        for (int nt = 0; nt < 4; nt++) {
            int row = am0 + m0 + mt * 16 + gid;
            int col = bn0 + n0 + nt * 8 + tid4 * 2;
            float v0 = acc[mt][nt][0], v1 = acc[mt][nt][1];
            float v2 = acc[mt][nt][2], v3 = acc[mt][nt][3];
            if (act) {
                v0 = softplus_f(v0); v1 = softplus_f(v1);
                v2 = softplus_f(v2); v3 = softplus_f(v3);
            }
            *(float2*)&out[(size_t)row * DDIM + col] = make_float2(v0, v1);
            *(float2*)&out[(size_t)(row + 8) * DDIM + col] = make_float2(v2, v3);
        }
    }
}

// ---------------------------------------------------------------------------
// Kernel B: per-chunk KV state via warp mma. Chunks 0..6 only (7 unused).
// ---------------------------------------------------------------------------
__global__ __launch_bounds__(512) void chunk_state_kernel(const float* __restrict__ pw) {
    extern __shared__ __align__(16) float smB[];
    float* sKf = smB;                // [t][f] stride SFT
    float* sV  = smB + 128*SFT;      // [t][e] stride SVE

    const int nh = blockIdx.x, c = blockIdx.y;
    const int n = nh >> 3, h = nh & 7;
    const int tid = threadIdx.x;
    const int wid = tid >> 5, lane = tid & 31;
    const int gid = lane >> 2, tid4 = lane & 3;

    for (int idx = tid; idx < 128*64; idx += 512) {
        int t = idx >> 6, di = idx & 63;
        int tg = c * TCH + t;
        int gbase = ((n << 10) + tg) * DDIM + (h << 6) + di;
        float kv = g_K[gbase];
        float vv = g_V[gbase];
        float w  = pw[(h << 6) + di];
        float s, cs;
        sincosf((float)tg * w, &s, &cs);
        sKf[t*SFT + di]      = f2tf_f(kv * cs);
        sKf[t*SFT + 64 + di] = f2tf_f(kv * s);
        sV[t*SVE + di]       = f2tf_f(vv);
    }
    __syncthreads();

    const uint32_t* sKf32 = (const uint32_t*)sKf;
    const uint32_t* sV32  = (const uint32_t*)sV;
    const int m0 = (wid & 3) * 32;
    const int n0 = (wid >> 2) * 16;
    float acc[2][2][4] = {};
#pragma unroll
    for (int k8 = 0; k8 < 16; k8++) {
        const int kk = k8 * 8 + tid4;
        uint32_t af[2][4];
#pragma unroll
        for (int mt = 0; mt < 2; mt++) {
            int r = m0 + mt * 16 + gid;
            af[mt][0] = sKf32[kk*SFT + r];
            af[mt][1] = sKf32[kk*SFT + r + 8];
            af[mt][2] = sKf32[(kk+4)*SFT + r];
            af[mt][3] = sKf32[(kk+4)*SFT + r + 8];
        }
        uint32_t bf[2][2];
#pragma unroll
        for (int nt = 0; nt < 2; nt++) {
            int nn = n0 + nt * 8 + gid;
            bf[nt][0] = sV32[kk*SVE + nn];
            bf[nt][1] = sV32[(kk+4)*SVE + nn];
        }
#pragma unroll
        for (int mt = 0; mt < 2; mt++)
#pragma unroll
            for (int nt = 0; nt < 2; nt++)
                mma_tf32(acc[mt][nt], af[mt], bf[nt]);
    }
    size_t base = (size_t)(nh * NCH + c) * SROW;
#pragma unroll
    for (int mt = 0; mt < 2; mt++) {
#pragma unroll
        for (int nt = 0; nt < 2; nt++) {
            int f = m0 + mt * 16 + gid;
            int e = n0 + nt * 8 + tid4 * 2;
            *(float2*)&g_S[base + (size_t)f * 64 + e] =
                make_float2(acc[mt][nt][0], acc[mt][nt][1]);
            *(float2*)&g_S[base + (size_t)(f + 8) * 64 + e] =
                make_float2(acc[mt][nt][2], acc[mt][nt][3]);
        }
    }
    if (tid < 128) {
        float s = 0.0f;
        for (int t = 0; t < 128; t++) s += sKf[t*SFT + tid];
        g_S[base + 8192 + tid] = s;
    }
}

// ---------------------------------------------------------------------------
// Kernel C: prefix scan of chunk states. g_SP[c] = sum_{cp<c} g_S[cp].
// One thread per state element; 7 independent loads batched (MLP=7).
// ---------------------------------------------------------------------------
__global__ __launch_bounds__(256) void scan_state_kernel() {
    const int idx = blockIdx.x * 256 + threadIdx.x;
    if (idx >= SROW) return;
    const size_t base = (size_t)blockIdx.y * NCH * SROW + idx;
    float v0 = g_S[base + 0*SROW];
    float v1 = g_S[base + 1*SROW];
    float v2 = g_S[base + 2*SROW];
    float v3 = g_S[base + 3*SROW];
    float v4 = g_S[base + 4*SROW];
    float v5 = g_S[base + 5*SROW];
    float v6 = g_S[base + 6*SROW];
    float r1 = v0;
    float r2 = r1 + v1;
    float r3 = r2 + v2;
    float r4 = r3 + v3;
    float r5 = r4 + v4;
    float r6 = r5 + v5;
    float r7 = r6 + v6;
    g_SP[base + 1*SROW] = r1;
    g_SP[base + 2*SROW] = r2;
    g_SP[base + 3*SROW] = r3;
    g_SP[base + 4*SROW] = r4;
    g_SP[base + 5*SROW] = r5;
    g_SP[base + 6*SROW] = r6;
    g_SP[base + 7*SROW] = r7;
}

// ---------------------------------------------------------------------------
// Kernel D: per-chunk output, all GEMMs raw-bit warp mma. 512 threads.
// ---------------------------------------------------------------------------
__global__ __launch_bounds__(512, 1) void attn_out_kernel(
        const float* __restrict__ pw, const float* __restrict__ pb,
        const float* __restrict__ coeff, float* __restrict__ out) {
    extern __shared__ __align__(16) float smD[];
    float* sQT   = smD;
    float* sKT   = smD + 17408;
    float* sV    = smD + 34816;
    float* sP    = smD + 44032;
    float* sPden = smD + 53248;
    float* sDen  = smD + 53376;
    float* sCB   = smD + 53504;
    float* sSB   = smD + 53568;

    const int nh = blockIdx.x, c = blockIdx.y;
    const int n = nh >> 3, h = nh & 7;
    const int tid = threadIdx.x;
    const int wid = tid >> 5, lane = tid & 31;
    const int gid = lane >> 2, tid4 = lane & 3;

    if (tid < 128) sDen[tid] = 0.0f;
    if (tid >= 128 && tid < 192) {
        int di = tid - 128;
        float sb_, cb_;
        sincosf(pb[(h << 6) + di], &sb_, &cb_);
        sCB[di] = cb_; sSB[di] = sb_;
    }
    __syncthreads();

    // Phase 1a: features + V (one accurate sincos per element + rotation)
    for (int idx = tid; idx < 128*64; idx += 512) {
        int t = idx >> 6, di = idx & 63;
        int tg = c * TCH + t;
        int gbase = ((n << 10) + tg) * DDIM + (h << 6) + di;
        float qv = g_Q[gbase], kv = g_K[gbase], vv = g_V[gbase];
        float w  = pw[(h << 6) + di];
        float cf = coeff[(h << 6) + di];
        float sk, ck;
        sincosf((float)tg * w, &sk, &ck);
        float cb_ = sCB[di], sb_ = sSB[di];
        float cq = ck * cb_ - sk * sb_;
        float sq = sk * cb_ + ck * sb_;
        float qc = qv * cf;
        sQT[di*SFT + t]        = f2tf_f(qc * cq);
        sQT[(64 + di)*SFT + t] = f2tf_f(qc * sq);
        sKT[di*SFT + t]        = f2tf_f(kv * ck);
        sKT[(64 + di)*SFT + t] = f2tf_f(kv * sk);
        sV[t*SVE + di]         = f2tf_f(vv);
    }
    // Phase 1b: prefix state (single coalesced read of cumulative state)
    if (c > 0) {
        size_t base = ((size_t)nh * NCH + c) * SROW;
        for (int idx = tid; idx < 128*64; idx += 512) {
            int f = idx >> 6, e = idx & 63;
            sP[f*SVE + e] = f2tf_f(g_SP[base + idx]);
        }
        if (tid < 128) sPden[tid] = g_SP[base + 8192 + tid];
    }
    __syncthreads();

    const uint32_t* sQT32 = (const uint32_t*)sQT;
    const uint32_t* sKT32 = (const uint32_t*)sKT;
    const uint32_t* sV32  = (const uint32_t*)sV;
    const uint32_t* sP32  = (const uint32_t*)sP;

    // Phase 2: scores (128x128, k = feature 128)
    const int m2 = (wid & 3) * 32;
    const int n2 = (wid >> 2) * 32;
    float acc[2][4][4] = {};
#pragma unroll
    for (int k8 = 0; k8 < 16; k8++) {
        const int kk = k8 * 8 + tid4;
        uint32_t af[2][4];
#pragma unroll
        for (int mt = 0; mt < 2; mt++) {
            int r = m2 + mt * 16 + gid;
            af[mt][0] = sQT32[kk*SFT + r];
            af[mt][1] = sQT32[kk*SFT + r + 8];
            af[mt][2] = sQT32[(kk+4)*SFT + r];
            af[mt][3] = sQT32[(kk+4)*SFT + r + 8];
        }
        uint32_t bf[4][2];
#pragma unroll
        for (int nt = 0; nt < 4; nt++) {
            int nn = n2 + nt * 8 + gid;
            bf[nt][0] = sKT32[kk*SFT + nn];
            bf[nt][1] = sKT32[(kk+4)*SFT + nn];
        }
#pragma unroll
        for (int mt = 0; mt < 2; mt++)
#pragma unroll
            for (int nt = 0; nt < 4; nt++)
                mma_tf32(acc[mt][nt], af[mt], bf[nt]);
    }
    __syncthreads();   // all warps done reading sKT

    // Causal mask -> write transposed sAT[col][row] (round at store), row sums
    float* sAT = sKT;
#pragma unroll
    for (int mt = 0; mt < 2; mt++) {
        int r = m2 + mt * 16 + gid;
        float rs_lo = 0.0f, rs_hi = 0.0f;
#pragma unroll
        for (int nt = 0; nt < 4; nt++) {
            int cb = n2 + nt * 8 + tid4 * 2;
            float v0 = (cb     <= r)     ? acc[mt][nt][0] : 0.0f;
            float v1 = (cb + 1 <= r)     ? acc[mt][nt][1] : 0.0f;
            float v2 = (cb     <= r + 8) ? acc[mt][nt][2] : 0.0f;
            float v3 = (cb + 1 <= r + 8) ? acc[mt][nt][3] : 0.0f;
            sAT[cb * SFT + r]           = f2tf_f(v0);
            sAT[(cb + 1) * SFT + r]     = f2tf_f(v1);
            sAT[cb * SFT + r + 8]       = f2tf_f(v2);
            sAT[(cb + 1) * SFT + r + 8] = f2tf_f(v3);
            rs_lo += v0 + v1;
            rs_hi += v2 + v3;
        }
        atomicAdd(&sDen[r], rs_lo);
        atomicAdd(&sDen[r + 8], rs_hi);
    }
    __syncthreads();

    const uint32_t* sAT32 = (const uint32_t*)sAT;

    // Phase 3: out = A@V + PhiQ^T@P  (128x64), warp tile 32x16
    const int m3 = (wid & 3) * 32;
    const int n3 = (wid >> 2) * 16;
    float o[2][2][4] = {};
    // term 1: k = key index (A stored transposed -> column reads)
#pragma unroll
    for (int k8 = 0; k8 < 16; k8++) {
        const int kk = k8 * 8 + tid4;
        uint32_t af[2][4];
#pragma unroll
        for (int mt = 0; mt < 2; mt++) {
            int r = m3 + mt * 16 + gid;
            af[mt][0] = sAT32[kk*SFT + r];
            af[mt][1] = sAT32[kk*SFT + r + 8];
            af[mt][2] = sAT32[(kk+4)*SFT + r];
            af[mt][3] = sAT32[(kk+4)*SFT + r + 8];
        }
        uint32_t bf[2][2];
#pragma unroll
        for (int nt = 0; nt < 2; nt++) {
            int nn = n3 + nt * 8 + gid;
            bf[nt][0] = sV32[kk*SVE + nn];
            bf[nt][1] = sV32[(kk+4)*SVE + nn];
        }
#pragma unroll
        for (int mt = 0; mt < 2; mt++)
#pragma unroll
            for (int nt = 0; nt < 2; nt++)
                mma_tf32(o[mt][nt], af[mt], bf[nt]);
    }
    if (c > 0) {
        // term 2: k = feature
#pragma unroll
        for (int k8 = 0; k8 < 16; k8++) {
            const int kk = k8 * 8 + tid4;
            uint32_t af[2][4];
#pragma unroll
            for (int mt = 0; mt < 2; mt++) {
                int r = m3 + mt * 16 + gid;
                af[mt][0] = sQT32[kk*SFT + r];
                af[mt][1] = sQT32[kk*SFT + r + 8];
                af[mt][2] = sQT32[(kk+4)*SFT + r];
                af[mt][3] = sQT32[(kk+4)*SFT + r + 8];
            }
            uint32_t bf[2][2];
#pragma unroll
            for (int nt = 0; nt < 2; nt++) {
                int nn = n3 + nt * 8 + gid;
                bf[nt][0] = sP32[kk*SVE + nn];
                bf[nt][1] = sP32[(kk+4)*SVE + nn];
            }
#pragma unroll
            for (int mt = 0; mt < 2; mt++)
#pragma unroll
                for (int nt = 0; nt < 2; nt++)
                    mma_tf32(o[mt][nt], af[mt], bf[nt]);
        }
        // den inter-chunk term (fp32, 4-way split over f)
        int t = tid & 127, part = tid >> 7;
        float s = 0.0f;
        for (int f = part * 32; f < part * 32 + 32; f++)
            s += sQT[f*SFT + t] * sPden[f];
        atomicAdd(&sDen[t], s);
    }
    __syncthreads();

    // Phase 4: normalize + write (N, Lq, H*dh)
#pragma unroll
    for (int mt = 0; mt < 2; mt++) {
        int r = m3 + mt * 16 + gid;
        float inv_lo = 1.0f / sDen[r];
        float inv_hi = 1.0f / sDen[r + 8];
        int tg_lo = c * TCH + r;
        int tg_hi = tg_lo + 8;
#pragma unroll
        for (int nt = 0; nt < 2; nt++) {
            int e = n3 + nt * 8 + tid4 * 2;
            *(float2*)&out[((n << 10) + tg_lo) * DDIM + (h << 6) + e] =
                make_float2(o[mt][nt][0] * inv_lo, o[mt][nt][1] * inv_lo);
            *(float2*)&out[((n << 10) + tg_hi) * DDIM + (h << 6) + e] =
                make_float2(o[mt][nt][2] * inv_hi, o[mt][nt][3] * inv_hi);
        }
    }
}

// ---------------------------------------------------------------------------
extern "C" void kernel_launch(void* const* d_in, const int* in_sizes, int n_in,
                              void* d_out, int out_size) {
    const float* query = (const float*)d_in[0];
    const float* key   = (const float*)d_in[1];
    const float* Wq    = (const float*)d_in[2];
    const float* Wk    = (const float*)d_in[3];
    const float* Wv    = (const float*)d_in[4];
    const float* coeff = (const float*)d_in[5];
    const float* pw    = (const float*)d_in[6];
    const float* pb    = (const float*)d_in[7];
    float* out = (float*)d_out;

    cudaFuncSetAttribute(proj_mma_kernel,
                         cudaFuncAttributeMaxDynamicSharedMemorySize, 49152);
    cudaFuncSetAttribute(chunk_state_kernel,
                         cudaFuncAttributeMaxDynamicSharedMemorySize, 107520);
    cudaFuncSetAttribute(attn_out_kernel,
                         cudaFuncAttributeMaxDynamicSharedMemorySize, 214528);

    conv_tf32_kernel<<<dim3(DDIM*DDIM/4/256, 3), 256>>>(Wq, Wk, Wv);
    proj_mma_kernel<<<dim3(MROWS/128, DDIM/64, 3), 256, 49152>>>(query, key);
    chunk_state_kernel<<<dim3(NHH, NCH-1), 512, 107520>>>(pw);
    scan_state_kernel<<<dim3((SROW + 255)/256, NHH), 256>>>();
    attn_out_kernel<<<dim3(NHH, NCH), 512, 214528>>>(pw, pb, coeff, out);
}